// round 4
// baseline (speedup 1.0000x reference)
#include <cuda_runtime.h>
#include <cstdint>

// ============================================================================
// myVMLSTMCell fused low-rank LSTM — fp32 / f32x2, dup-A smem + cp.async pipe.
// R4: fix grp1 dup-A offset (4096, not 8192); skip redundant grp1 for ch<2.
// ============================================================================

typedef unsigned long long ull;

#define NB 8192
#define NH 1024
#define KA 320
#define KW 192

// stage2 smem: W dbl-buf 2*16384 + dupA dbl-buf 2*8192 floats = 192 KB
#define S2_SMEM ((2*16384 + 2*8192)*4)

__device__ float g_AT[KA*NB];        // transposed scratch [col][b]
__device__ float g_W[4*KW*NH];       // merged weights
__device__ float g_cx[4*NH];
__device__ float g_ch[4*NH];
__device__ float g_cb[4*NH];

// ---- helpers ---------------------------------------------------------------
__device__ __forceinline__ ull pk2(float lo, float hi) {
    ull r; asm("mov.b64 %0, {%1,%2};" : "=l"(r) : "f"(lo), "f"(hi)); return r;
}
__device__ __forceinline__ void upk2(ull v, float& lo, float& hi) {
    asm("mov.b64 {%0,%1}, %2;" : "=f"(lo), "=f"(hi) : "l"(v));
}
__device__ __forceinline__ void fma2(ull& d, ull a, ull b) {
    asm("fma.rn.f32x2 %0, %1, %2, %3;" : "=l"(d) : "l"(a), "l"(b), "l"(d));
}
__device__ __forceinline__ float sigm_f(float v) {
    return __fdividef(1.f, 1.f + __expf(-v));
}
__device__ __forceinline__ float tanh_f(float v) {
    return 1.f - __fdividef(2.f, 1.f + __expf(2.f * v));
}
__device__ __forceinline__ uint32_t s2u(const void* p) {
    return (uint32_t)__cvta_generic_to_shared(p);
}
__device__ __forceinline__ void cp16(uint32_t dst, const void* src) {
    asm volatile("cp.async.cg.shared.global [%0], [%1], 16;\n"
                 :: "r"(dst), "l"(src));
}
__device__ __forceinline__ void cp_commit() {
    asm volatile("cp.async.commit_group;\n");
}
__device__ __forceinline__ void cp_wait0() {
    asm volatile("cp.async.wait_group 0;\n");
}

// ============================================================================
// Kernel A1: pack merged expansion weights g_W[kappa][kk][j]
// ============================================================================
__global__ void pack_w_kernel(const float* __restrict__ Vx,
                              const float* __restrict__ Vh0,
                              const float* __restrict__ Vh1) {
    int idx = blockIdx.x * 256 + threadIdx.x;
    if (idx >= 4 * KW * NH) return;
    int j   = idx & 1023;
    int kk  = (idx >> 10) % KW;
    int kap = idx / (KW * NH);
    int g   = kap >> 1;
    int mh  = (((kap ^ 1) & 1) << 10) + j;
    float v;
    if (kk < 64)        v = Vx[(kap * NH + j) * 64 + kk];
    else if (kk < 128)  v = Vh0[g * 131072 + (kk - 64) * 2048 + mh];
    else                v = Vh1[g * 131072 + (kk - 128) * 2048 + mh];
    g_W[idx] = v;
}

// ============================================================================
// Kernel A2: coef_x, coef_h (permuted), combined bias
// ============================================================================
__global__ void coef_kernel(const float* __restrict__ Ux,
                            const float* __restrict__ Vx,
                            const float* __restrict__ Uh0,
                            const float* __restrict__ Vh0,
                            const float* __restrict__ bx,
                            const float* __restrict__ bh) {
    int idx = blockIdx.x * 256 + threadIdx.x;
    if (idx >= 4 * NH) return;
    int j = idx & 1023;
    int kap = idx >> 10;
    int g  = kap >> 1;
    int mh = (((kap ^ 1) & 1) << 10) + j;
    float sx = 0.f, sh = 0.f;
    #pragma unroll 8
    for (int r = 0; r < 64; r++) {
        sx += Ux[j * 64 + r] * Vx[(kap * NH + j) * 64 + r];
        sh += Uh0[j * 64 + r] * Vh0[g * 131072 + r * 2048 + mh];
    }
    g_cx[idx] = sx;
    g_ch[idx] = sh;
    g_cb[idx] = bx[(kap << 10) + j] + bh[((kap ^ 1) << 10) + j];
}

// ============================================================================
// Kernel B: stage-1 contractions -> g_AT[col][b]
//   grid (64 b-tiles of 128, 5 col-blocks of 64), 256 threads
//   thread: tx -> 2 n cols, ty -> 16 b rows (8 b-pairs); acc[8bp][2n]
//   A operand = natural b-pair f32x2 (no pack); W packed 2x per kk.
// ============================================================================
__global__ __launch_bounds__(256) void stage1_kernel(
        const float* __restrict__ x, const float* __restrict__ h,
        const float* __restrict__ Ux, const float* __restrict__ Uh0,
        const float* __restrict__ Uh1) {
    __shared__ float Xs[64 * 132];   // phase A: [kk][128 b] swizzled (stride 128)
    __shared__ float Ws[64 * 64];

    int cb = blockIdx.y;
    const float* Ap; const float* Wp;
    int K, outoff, aoff;
    if (cb == 0) {
        Ap = x; Wp = Ux; K = 1024; outoff = 0; aoff = 0;
    } else {
        int e = cb - 1;
        int g = e >> 1, i = e & 1;
        Ap = h; Wp = (i ? Uh1 : Uh0) + g * 512 * 64;
        K = 512; outoff = 64 + g * 128 + i * 64;
        aoff = ((g + i) & 1) * 512;
    }
    int tid = threadIdx.x, tx = tid & 31, ty = tid >> 5;
    int b0 = blockIdx.x * 128;

    ull acc[8][2];
    #pragma unroll
    for (int p = 0; p < 8; p++) { acc[p][0] = 0ull; acc[p][1] = 0ull; }

    for (int k0 = 0; k0 < K; k0 += 64) {
        // X fill: swizzled transpose, 2-way conflicts
        #pragma unroll
        for (int i2 = 0; i2 < 8; i2++) {
            int idx = tid + i2 * 256;           // 2048 float4
            int r = idx >> 4, c4 = idx & 15;
            float4 v = *(const float4*)&Ap[(size_t)(b0 + r) * NH + aoff + k0 + c4 * 4];
            float vv[4] = {v.x, v.y, v.z, v.w};
            #pragma unroll
            for (int q = 0; q < 4; q++) {
                int kk = c4 * 4 + q;
                int swz = (kk >> 2) & 7;
                Xs[kk * 128 + (((r >> 2) ^ swz) << 2) + (r & 3)] = vv[q];
            }
        }
        // W fill
        #pragma unroll
        for (int i2 = 0; i2 < 4; i2++) {
            int idx = tid + i2 * 256;           // 1024 float4
            int kk = idx >> 4, n4 = idx & 15;
            *(float4*)&Ws[kk * 64 + n4 * 4] =
                *(const float4*)&Wp[(size_t)(k0 + kk) * 64 + n4 * 4];
        }
        __syncthreads();
        #pragma unroll 4
        for (int kk = 0; kk < 64; kk++) {
            float2 wv = *(const float2*)&Ws[kk * 64 + tx * 2];
            ull w0 = pk2(wv.x, wv.x), w1 = pk2(wv.y, wv.y);
            int swz = (kk >> 2) & 7;
            ull a[8];
            #pragma unroll
            for (int j = 0; j < 4; j++) {
                ulonglong2 av = *(const ulonglong2*)
                    &Xs[kk * 128 + (((ty * 4 + j) ^ swz) << 2)];
                a[2 * j] = av.x; a[2 * j + 1] = av.y;
            }
            #pragma unroll
            for (int p = 0; p < 8; p++) {
                fma2(acc[p][0], a[p], w0);
                fma2(acc[p][1], a[p], w1);
            }
        }
        __syncthreads();
    }

    // transpose to Ts[n][b] (stride 132) then coalesced STG
    float* Ts = Xs;
    #pragma unroll
    for (int n = 0; n < 2; n++)
        #pragma unroll
        for (int p = 0; p < 8; p++) {
            float lo, hi; upk2(acc[p][n], lo, hi);
            int nl = tx * 2 + n, bl = ty * 16 + p * 2;
            *(float2*)&Ts[nl * 132 + bl] = make_float2(lo, hi);
        }
    __syncthreads();
    #pragma unroll
    for (int i2 = 0; i2 < 8; i2++) {
        int idx = tid + i2 * 256;               // 2048 float4
        int nl = idx >> 5, b4 = idx & 31;
        float4 v = *(const float4*)&Ts[nl * 132 + b4 * 4];
        *(float4*)&g_AT[(size_t)(outoff + nl) * NB + b0 + b4 * 4] = v;
    }
}

// ============================================================================
// Kernel C: stage-2 expansion GEMM (K=192) + fused LSTM epilogue
//   block 64 b x 128 j, grid (8,128), 256 thr, 192 KB smem
//   dup-A smem (values pre-packed (a,a)); cp.async double-buffered W.
//   Per buffer Ad layout: grp0 [0,4096) floats, grp1 [4096,8192) floats.
//   thread: tx -> 4 j (2 f32x2), ty -> 8 b; acc[8b][4g][2jp]
// ============================================================================
__global__ __launch_bounds__(256, 1) void stage2_kernel(
        const float* __restrict__ x, const float* __restrict__ h,
        const float* __restrict__ c, const float* __restrict__ dia_x,
        const float* __restrict__ dia_h, float* __restrict__ out) {
    extern __shared__ float sm[];
    // layout: Ws[2][16384], Ad[2][8192]
    float* WsB[2] = {sm, sm + 16384};
    float* AdB[2] = {sm + 32768, sm + 32768 + 8192};
    uint32_t ws_u[2] = {s2u(WsB[0]), s2u(WsB[1])};
    uint32_t ad_u[2] = {s2u(AdB[0]), s2u(AdB[1])};

    int j0 = blockIdx.x * 128;
    int b0 = blockIdx.y * 64;
    int tid = threadIdx.x, tx = tid & 31, ty = tid >> 5;

    float2 pref[2][4];

    #define ISSUE_W(ch, buf) do {                                             \
        uint32_t dstb = ws_u[buf];                                            \
        _Pragma("unroll")                                                     \
        for (int i2 = 0; i2 < 16; i2++) {                                     \
            int idx = tid + i2 * 256;                                         \
            int row = idx >> 5, off = idx & 31;                               \
            int gg = row & 3, kkL = row >> 2;                                 \
            cp16(dstb + idx * 16,                                             \
                 &g_W[(size_t)gg * (KW * NH) + ((ch) * 32 + kkL) * NH +       \
                      j0 + off * 4]);                                         \
        }                                                                     \
        cp_commit();                                                          \
    } while (0)

    // grp1 only needed for ch>=2 (phase 2 reads two A slabs)
    #define LDG_A(ch) do {                                                    \
        int ngrp = ((ch) >= 2) ? 2 : 1;                                       \
        for (int grp = 0; grp < ngrp; grp++) {                                \
            int rsh = (grp == 1) ? 128 : 0;                                   \
            _Pragma("unroll")                                                 \
            for (int i2 = 0; i2 < 4; i2++) {                                  \
                int p = i2 * 512 + tid * 2;                                   \
                int kk = p >> 6, bb = p & 63;                                 \
                pref[grp][i2] = *(const float2*)                              \
                    &g_AT[(size_t)((ch) * 32 + kk + rsh) * NB + b0 + bb];     \
            }                                                                 \
        }                                                                     \
    } while (0)

    #define STS_A(buf, ch) do {                                               \
        int ngrp = ((ch) >= 2) ? 2 : 1;                                       \
        for (int grp = 0; grp < ngrp; grp++)                                  \
            _Pragma("unroll")                                                 \
            for (int i2 = 0; i2 < 4; i2++) {                                  \
                int p = i2 * 512 + tid * 2;                                   \
                float2 v = pref[grp][i2];                                     \
                uint32_t ad = ad_u[buf] + grp * 16384 + p * 8;                \
                asm volatile(                                                 \
                    "st.shared.v4.f32 [%0], {%1,%1,%2,%2};\n"                 \
                    :: "r"(ad), "f"(v.x), "f"(v.y));                          \
            }                                                                 \
    } while (0)

    ull acc[8][4][2];
    #pragma unroll
    for (int b = 0; b < 8; b++)
        #pragma unroll
        for (int g = 0; g < 4; g++) { acc[b][g][0] = 0ull; acc[b][g][1] = 0ull; }

    // prologue
    ISSUE_W(0, 0);
    LDG_A(0);
    STS_A(0, 0);
    cp_wait0();
    __syncthreads();

    for (int ch = 0; ch < 6; ch++) {
        int buf = ch & 1;
        if (ch < 5) { ISSUE_W(ch + 1, buf ^ 1); LDG_A(ch + 1); }

        const ulonglong2* Wv = (const ulonglong2*)WsB[buf];
        const float* Ad = AdB[buf];

        if (ch < 2) {
            #pragma unroll 2
            for (int kkL = 0; kkL < 32; kkL++) {
                ulonglong2 w0 = Wv[(kkL * 4 + 0) * 32 + tx];
                ulonglong2 w1 = Wv[(kkL * 4 + 1) * 32 + tx];
                ulonglong2 w2 = Wv[(kkL * 4 + 2) * 32 + tx];
                ulonglong2 w3 = Wv[(kkL * 4 + 3) * 32 + tx];
                const ulonglong2* ar =
                    (const ulonglong2*)&Ad[(kkL * 64 + ty * 8) * 2];
                ulonglong2 q0 = ar[0], q1 = ar[1], q2 = ar[2], q3 = ar[3];
                ull a[8] = {q0.x, q0.y, q1.x, q1.y, q2.x, q2.y, q3.x, q3.y};
                #pragma unroll
                for (int b = 0; b < 8; b++) {
                    fma2(acc[b][0][0], a[b], w0.x); fma2(acc[b][0][1], a[b], w0.y);
                    fma2(acc[b][1][0], a[b], w1.x); fma2(acc[b][1][1], a[b], w1.y);
                    fma2(acc[b][2][0], a[b], w2.x); fma2(acc[b][2][1], a[b], w2.y);
                    fma2(acc[b][3][0], a[b], w3.x); fma2(acc[b][3][1], a[b], w3.y);
                }
            }
        } else {
            #pragma unroll 2
            for (int kkL = 0; kkL < 32; kkL++) {
                ulonglong2 w0 = Wv[(kkL * 4 + 0) * 32 + tx];
                ulonglong2 w1 = Wv[(kkL * 4 + 1) * 32 + tx];
                ulonglong2 w2 = Wv[(kkL * 4 + 2) * 32 + tx];
                ulonglong2 w3 = Wv[(kkL * 4 + 3) * 32 + tx];
                const ulonglong2* a0r =
                    (const ulonglong2*)&Ad[(kkL * 64 + ty * 8) * 2];
                const ulonglong2* a1r =
                    (const ulonglong2*)&Ad[4096 + (kkL * 64 + ty * 8) * 2];
                ulonglong2 p0 = a0r[0], p1 = a0r[1], p2 = a0r[2], p3 = a0r[3];
                ulonglong2 r0 = a1r[0], r1 = a1r[1], r2 = a1r[2], r3 = a1r[3];
                ull a0[8] = {p0.x, p0.y, p1.x, p1.y, p2.x, p2.y, p3.x, p3.y};
                ull a1[8] = {r0.x, r0.y, r1.x, r1.y, r2.x, r2.y, r3.x, r3.y};
                #pragma unroll
                for (int b = 0; b < 8; b++) {
                    fma2(acc[b][0][0], a0[b], w0.x); fma2(acc[b][0][1], a0[b], w0.y);
                    fma2(acc[b][1][0], a0[b], w1.x); fma2(acc[b][1][1], a0[b], w1.y);
                    fma2(acc[b][2][0], a1[b], w2.x); fma2(acc[b][2][1], a1[b], w2.y);
                    fma2(acc[b][3][0], a1[b], w3.x); fma2(acc[b][3][1], a1[b], w3.y);
                }
            }
        }

        if (ch < 5) { STS_A(buf ^ 1, ch + 1); cp_wait0(); }
        __syncthreads();
    }

    // ---- fused LSTM epilogue -----------------------------------------------
    int j = j0 + tx * 4;
    float4 dxv = *(const float4*)&dia_x[j];
    float4 dhv = *(const float4*)&dia_h[j];
    float dx[4] = {dxv.x, dxv.y, dxv.z, dxv.w};
    float dh[4] = {dhv.x, dhv.y, dhv.z, dhv.w};
    float cx[4][4], chv[4][4], cb[4][4];
    #pragma unroll
    for (int k = 0; k < 4; k++) {
        float4 a = *(const float4*)&g_cx[(k << 10) + j];
        float4 bq = *(const float4*)&g_ch[(k << 10) + j];
        float4 cq = *(const float4*)&g_cb[(k << 10) + j];
        cx[k][0] = a.x;  cx[k][1] = a.y;  cx[k][2] = a.z;  cx[k][3] = a.w;
        chv[k][0] = bq.x; chv[k][1] = bq.y; chv[k][2] = bq.z; chv[k][3] = bq.w;
        cb[k][0] = cq.x; cb[k][1] = cq.y; cb[k][2] = cq.z; cb[k][3] = cq.w;
    }
    #pragma unroll
    for (int b = 0; b < 8; b++) {
        int row = b0 + ty * 8 + b;
        size_t off = (size_t)row * NH + j;
        float4 xv = *(const float4*)&x[off];
        float4 hv = *(const float4*)&h[off];
        float4 cv = *(const float4*)&c[off];
        float xa[4] = {xv.x, xv.y, xv.z, xv.w};
        float ha[4] = {hv.x, hv.y, hv.z, hv.w};
        float ca[4] = {cv.x, cv.y, cv.z, cv.w};
        float gg[4][4];
        #pragma unroll
        for (int g = 0; g < 4; g++) {
            float lo, hi;
            upk2(acc[b][g][0], lo, hi); gg[g][0] = lo; gg[g][1] = hi;
            upk2(acc[b][g][1], lo, hi); gg[g][2] = lo; gg[g][3] = hi;
        }
        float hn[4], cn[4];
        #pragma unroll
        for (int jj = 0; jj < 4; jj++) {
            float base = dx[jj] * xa[jj] + dh[jj] * ha[jj];
            float v0 = gg[0][jj] - xa[jj] * cx[0][jj] - ha[jj] * chv[0][jj] + cb[0][jj] + base;
            float v1 = gg[1][jj] - xa[jj] * cx[1][jj] - ha[jj] * chv[1][jj] + cb[1][jj] + base;
            float v2 = gg[2][jj] - xa[jj] * cx[2][jj] - ha[jj] * chv[2][jj] + cb[2][jj] + base;
            float v3 = gg[3][jj] - xa[jj] * cx[3][jj] - ha[jj] * chv[3][jj] + cb[3][jj] + base;
            float ig = sigm_f(v0);
            float fg = sigm_f(v1);
            float og = sigm_f(v2);
            float ng = tanh_f(v3);
            float cnx = fg * ca[jj] + ig * ng;
            cn[jj] = cnx;
            hn[jj] = og * tanh_f(cnx);
        }
        *(float4*)&out[off] = make_float4(hn[0], hn[1], hn[2], hn[3]);
        *(float4*)&out[(size_t)NB * NH + off] = make_float4(cn[0], cn[1], cn[2], cn[3]);
    }
}

// ============================================================================
extern "C" void kernel_launch(void* const* d_in, const int* in_sizes, int n_in,
                              void* d_out, int out_size) {
    const float* x     = (const float*)d_in[0];
    const float* h     = (const float*)d_in[1];
    const float* c     = (const float*)d_in[2];
    const float* dia_x = (const float*)d_in[3];
    const float* dia_h = (const float*)d_in[4];
    const float* Ux    = (const float*)d_in[5];
    const float* Vx    = (const float*)d_in[6];
    const float* Uh0   = (const float*)d_in[7];
    const float* Vh0   = (const float*)d_in[8];
    const float* Uh1   = (const float*)d_in[9];
    const float* Vh1   = (const float*)d_in[10];
    const float* bx    = (const float*)d_in[11];
    const float* bh    = (const float*)d_in[12];
    float* out = (float*)d_out;

    cudaFuncSetAttribute(stage2_kernel,
                         cudaFuncAttributeMaxDynamicSharedMemorySize, S2_SMEM);

    pack_w_kernel<<<(4 * KW * NH + 255) / 256, 256>>>(Vx, Vh0, Vh1);
    coef_kernel<<<16, 256>>>(Ux, Vx, Uh0, Vh0, bx, bh);
    stage1_kernel<<<dim3(64, 5), 256>>>(x, h, Ux, Uh0, Uh1);
    stage2_kernel<<<dim3(8, 128), 256, S2_SMEM>>>(x, h, c, dia_x, dia_h, out);
}

// round 7
// speedup vs baseline: 1.3050x; 1.3050x over previous
#include <cuda_runtime.h>
#include <cuda_bf16.h>
#include <cstdint>

// ============================================================================
// myVMLSTMCell fused low-rank LSTM — R7: stage2 on mma.sync bf16 (2-split x3).
//   pack:   g_Wh/g_Wl  [gate][j][96 kpairs] u32 (2 bf16 each), coefs fp32.
//   stage1: FFMA2 contractions -> g_Ah/g_Al [b][160 kpairs] u32 bf16-split.
//   stage2: per CTA 64b x 64j: 2 phases (gates i,f then o,n), K=192 each,
//           m16n8k16 bf16 MMA, 3 passes (hh, lh, hl), cp.async dbl-buffer,
//           fused LSTM epilogue from register accumulators.
// ============================================================================

typedef unsigned long long ull;

#define NB 8192
#define NH 1024

__device__ uint32_t g_Ah[NB*160];      // bf16 hi pairs [b][kpair]
__device__ uint32_t g_Al[NB*160];      // bf16 lo pairs
__device__ uint32_t g_Wh[4*1024*96];   // [gate][j][kpair]
__device__ uint32_t g_Wl[4*1024*96];
__device__ float g_cx[4*NH];
__device__ float g_ch[4*NH];
__device__ float g_cb[4*NH];

// ---- scalar helpers --------------------------------------------------------
__device__ __forceinline__ ull pk2(float lo, float hi) {
    ull r; asm("mov.b64 %0, {%1,%2};" : "=l"(r) : "f"(lo), "f"(hi)); return r;
}
__device__ __forceinline__ void upk2(ull v, float& lo, float& hi) {
    asm("mov.b64 {%0,%1}, %2;" : "=f"(lo), "=f"(hi) : "l"(v));
}
__device__ __forceinline__ void fma2(ull& d, ull a, ull b) {
    asm("fma.rn.f32x2 %0, %1, %2, %3;" : "=l"(d) : "l"(a), "l"(b), "l"(d));
}
__device__ __forceinline__ float sigm_f(float v) {
    return __fdividef(1.f, 1.f + __expf(-v));
}
__device__ __forceinline__ float tanh_f(float v) {
    return 1.f - __fdividef(2.f, 1.f + __expf(2.f * v));
}
// split v -> bf16 hi/lo, return packed u16 pair
__device__ __forceinline__ void bfsplit(float v, uint16_t& h, uint16_t& l) {
    __nv_bfloat16 bh = __float2bfloat16_rn(v);
    float r = v - __bfloat162float(bh);
    __nv_bfloat16 bl = __float2bfloat16_rn(r);
    h = __bfloat16_as_ushort(bh);
    l = __bfloat16_as_ushort(bl);
}
__device__ __forceinline__ uint32_t s2u(const void* p) {
    return (uint32_t)__cvta_generic_to_shared(p);
}
__device__ __forceinline__ void cp16(uint32_t dst, const void* src) {
    asm volatile("cp.async.cg.shared.global [%0], [%1], 16;\n"
                 :: "r"(dst), "l"(src));
}
__device__ __forceinline__ void cp_commit() {
    asm volatile("cp.async.commit_group;\n");
}
__device__ __forceinline__ void cp_wait0() {
    asm volatile("cp.async.wait_group 0;\n");
}
__device__ __forceinline__ uint32_t lds32(uint32_t a) {
    uint32_t v;
    asm volatile("ld.shared.b32 %0, [%1];" : "=r"(v) : "r"(a));
    return v;
}
__device__ __forceinline__ void mma_bf16(float* d, const uint32_t* a,
                                         const uint32_t* b) {
    asm volatile(
        "mma.sync.aligned.m16n8k16.row.col.f32.bf16.bf16.f32 "
        "{%0,%1,%2,%3}, {%4,%5,%6,%7}, {%8,%9}, {%0,%1,%2,%3};\n"
        : "+f"(d[0]), "+f"(d[1]), "+f"(d[2]), "+f"(d[3])
        : "r"(a[0]), "r"(a[1]), "r"(a[2]), "r"(a[3]), "r"(b[0]), "r"(b[1]));
}

// ============================================================================
// Kernel A1: pack split weights g_Wh/g_Wl[gate][j][kpair]
// ============================================================================
__global__ void pack_w_kernel(const float* __restrict__ Vx,
                              const float* __restrict__ Vh0,
                              const float* __restrict__ Vh1) {
    int idx = blockIdx.x * 256 + threadIdx.x;
    if (idx >= 4 * 1024 * 96) return;
    int kp  = idx % 96;
    int j   = (idx / 96) & 1023;
    int kap = idx / (96 * 1024);
    int g   = kap >> 1;
    int mh  = (((kap ^ 1) & 1) << 10) + j;
    uint16_t h[2], l[2];
    #pragma unroll
    for (int e = 0; e < 2; e++) {
        int kk = kp * 2 + e;
        float v;
        if (kk < 64)        v = Vx[(kap * NH + j) * 64 + kk];
        else if (kk < 128)  v = Vh0[g * 131072 + (kk - 64) * 2048 + mh];
        else                v = Vh1[g * 131072 + (kk - 128) * 2048 + mh];
        bfsplit(v, h[e], l[e]);
    }
    g_Wh[idx] = (uint32_t)h[0] | ((uint32_t)h[1] << 16);
    g_Wl[idx] = (uint32_t)l[0] | ((uint32_t)l[1] << 16);
}

// ============================================================================
// Kernel A2: coef_x, coef_h (permuted), combined bias
// ============================================================================
__global__ void coef_kernel(const float* __restrict__ Ux,
                            const float* __restrict__ Vx,
                            const float* __restrict__ Uh0,
                            const float* __restrict__ Vh0,
                            const float* __restrict__ bx,
                            const float* __restrict__ bh) {
    int idx = blockIdx.x * 256 + threadIdx.x;
    if (idx >= 4 * NH) return;
    int j = idx & 1023;
    int kap = idx >> 10;
    int g  = kap >> 1;
    int mh = (((kap ^ 1) & 1) << 10) + j;
    float sx = 0.f, sh = 0.f;
    #pragma unroll 8
    for (int r = 0; r < 64; r++) {
        sx += Ux[j * 64 + r] * Vx[(kap * NH + j) * 64 + r];
        sh += Uh0[j * 64 + r] * Vh0[g * 131072 + r * 2048 + mh];
    }
    g_cx[idx] = sx;
    g_ch[idx] = sh;
    g_cb[idx] = bx[(kap << 10) + j] + bh[((kap ^ 1) << 10) + j];
}

// ============================================================================
// Kernel B: stage-1 FFMA2 contractions -> g_Ah/g_Al (bf16-split pairs)
// ============================================================================
__global__ __launch_bounds__(256) void stage1_kernel(
        const float* __restrict__ x, const float* __restrict__ h,
        const float* __restrict__ Ux, const float* __restrict__ Uh0,
        const float* __restrict__ Uh1) {
    __shared__ float Xs[64 * 132];
    __shared__ float Ws[64 * 64];

    int cb = blockIdx.y;
    const float* Ap; const float* Wp;
    int K, outoff, aoff;
    if (cb == 0) {
        Ap = x; Wp = Ux; K = 1024; outoff = 0; aoff = 0;
    } else {
        int e = cb - 1;
        int g = e >> 1, i = e & 1;
        Ap = h; Wp = (i ? Uh1 : Uh0) + g * 512 * 64;
        K = 512; outoff = 64 + g * 128 + i * 64;
        aoff = ((g + i) & 1) * 512;
    }
    int tid = threadIdx.x, tx = tid & 31, ty = tid >> 5;
    int b0 = blockIdx.x * 128;

    ull acc[8][2];
    #pragma unroll
    for (int p = 0; p < 8; p++) { acc[p][0] = 0ull; acc[p][1] = 0ull; }

    for (int k0 = 0; k0 < K; k0 += 64) {
        #pragma unroll
        for (int i2 = 0; i2 < 8; i2++) {
            int idx = tid + i2 * 256;
            int r = idx >> 4, c4 = idx & 15;
            float4 v = *(const float4*)&Ap[(size_t)(b0 + r) * NH + aoff + k0 + c4 * 4];
            float vv[4] = {v.x, v.y, v.z, v.w};
            #pragma unroll
            for (int q = 0; q < 4; q++) {
                int kk = c4 * 4 + q;
                int swz = (kk >> 2) & 7;
                Xs[kk * 128 + (((r >> 2) ^ swz) << 2) + (r & 3)] = vv[q];
            }
        }
        #pragma unroll
        for (int i2 = 0; i2 < 4; i2++) {
            int idx = tid + i2 * 256;
            int kk = idx >> 4, n4 = idx & 15;
            *(float4*)&Ws[kk * 64 + n4 * 4] =
                *(const float4*)&Wp[(size_t)(k0 + kk) * 64 + n4 * 4];
        }
        __syncthreads();
        #pragma unroll 4
        for (int kk = 0; kk < 64; kk++) {
            float2 wv = *(const float2*)&Ws[kk * 64 + tx * 2];
            ull w0 = pk2(wv.x, wv.x), w1 = pk2(wv.y, wv.y);
            int swz = (kk >> 2) & 7;
            ull a[8];
            #pragma unroll
            for (int j = 0; j < 4; j++) {
                ulonglong2 av = *(const ulonglong2*)
                    &Xs[kk * 128 + (((ty * 4 + j) ^ swz) << 2)];
                a[2 * j] = av.x; a[2 * j + 1] = av.y;
            }
            #pragma unroll
            for (int p = 0; p < 8; p++) {
                fma2(acc[p][0], a[p], w0);
                fma2(acc[p][1], a[p], w1);
            }
        }
        __syncthreads();
    }

    // store bf16-split pairs: cols (tx*2, tx*2+1) for rows b, b+1
    int cw = (outoff >> 1) + tx;
    #pragma unroll
    for (int p = 0; p < 8; p++) {
        float lo0, hi0, lo1, hi1;
        upk2(acc[p][0], lo0, hi0);
        upk2(acc[p][1], lo1, hi1);
        int b = b0 + ty * 16 + p * 2;
        uint16_t h0, l0, h1, l1;
        bfsplit(lo0, h0, l0); bfsplit(lo1, h1, l1);
        g_Ah[(size_t)b * 160 + cw] = (uint32_t)h0 | ((uint32_t)h1 << 16);
        g_Al[(size_t)b * 160 + cw] = (uint32_t)l0 | ((uint32_t)l1 << 16);
        bfsplit(hi0, h0, l0); bfsplit(hi1, h1, l1);
        g_Ah[(size_t)(b + 1) * 160 + cw] = (uint32_t)h0 | ((uint32_t)h1 << 16);
        g_Al[(size_t)(b + 1) * 160 + cw] = (uint32_t)l0 | ((uint32_t)l1 << 16);
    }
}

// ============================================================================
// Kernel C: stage-2 bf16 mma.sync GEMM + fused LSTM epilogue
//   grid (16 j-tiles of 64, 128 b-tiles of 64), 256 threads (8 warps)
//   warp grid 2b x 4j: warp = 32b x 16j x 2 gates per phase
//   smem buffer (bytes): Ah 0..5120, Al 5120..10240, Wh 10240..20480,
//                        Wl 20480..30720; two buffers, stride 30720.
//   rows stride 20 u32 (80B) -> conflict-free frag loads.
// ============================================================================
#define S2_DSMEM (2*30720)

__global__ __launch_bounds__(256, 1)
void stage2_mma(const float* __restrict__ x, const float* __restrict__ h,
                const float* __restrict__ c, const float* __restrict__ dia_x,
                const float* __restrict__ dia_h, float* __restrict__ out) {
    extern __shared__ char dsm[];
    __shared__ float epi[896];   // cx[4][64] | ch | cb | dx[64] | dh[64]
    uint32_t smu = s2u(dsm);

    int tid = threadIdx.x;
    int lane = tid & 31, wid = tid >> 5;
    int tg = lane & 3, lrow = lane >> 2;
    int wb = wid >> 2, wj = wid & 3;
    int j0 = blockIdx.x * 64;
    int b0 = blockIdx.y * 64;

    for (int i = tid; i < 896; i += 256) {
        float v;
        if (i < 256)       v = g_cx[(i >> 6) * 1024 + j0 + (i & 63)];
        else if (i < 512)  { int q = i - 256; v = g_ch[(q >> 6) * 1024 + j0 + (q & 63)]; }
        else if (i < 768)  { int q = i - 512; v = g_cb[(q >> 6) * 1024 + j0 + (q & 63)]; }
        else if (i < 832)  v = dia_x[j0 + i - 768];
        else               v = dia_h[j0 + i - 832];
        epi[i] = v;
    }

    float acc0[2][2][2][4];   // phase0: [mt][nt][gate i/f][reg]
    float acc1[2][2][2][4];   // phase1: [mt][nt][gate o/n][reg]
    #pragma unroll
    for (int a1 = 0; a1 < 2; a1++)
        #pragma unroll
        for (int a2 = 0; a2 < 2; a2++)
            #pragma unroll
            for (int a3 = 0; a3 < 2; a3++)
                #pragma unroll
                for (int a4 = 0; a4 < 4; a4++) {
                    acc0[a1][a2][a3][a4] = 0.f;
                    acc1[a1][a2][a3][a4] = 0.f;
                }

    // ---- fill chunk (p, cc) into buffer buf ----
    #define FILL(buf, p, cc) do {                                             \
        int cbh = ((cc) < 2) ? (cc) * 16 : 64 * (p) + (cc) * 16;              \
        {   /* A: 64 rows x 4 quads, one cp16 each for hi and lo */           \
            int row = tid >> 2, q = tid & 3;                                  \
            uint32_t dst = smu + (buf) * 30720 + row * 80 + q * 16;           \
            size_t si = (size_t)(b0 + row) * 160 + cbh + q * 4;               \
            cp16(dst, &g_Ah[si]);                                             \
            cp16(dst + 5120, &g_Al[si]);                                      \
        }                                                                     \
        _Pragma("unroll")                                                     \
        for (int i2 = 0; i2 < 2; i2++) {                                      \
            int idx = tid + i2 * 256;                                         \
            int gl = idx >> 8, rem = idx & 255;                               \
            int n = rem >> 2, q = rem & 3;                                    \
            uint32_t dst = smu + (buf) * 30720 + 10240 +                      \
                           (gl * 64 + n) * 80 + q * 16;                       \
            size_t si = (size_t)((2 * (p) + gl) * 1024 + j0 + n) * 96 +       \
                        (cc) * 16 + q * 4;                                    \
            cp16(dst, &g_Wh[si]);                                             \
            cp16(dst + 10240, &g_Wl[si]);                                     \
        }                                                                     \
        cp_commit();                                                          \
    } while (0)

    // ---- compute one chunk (2 k16-steps) from buffer buf into ACC ----
    #define COMPUTE(ACC, buf) do {                                            \
        uint32_t bufb = smu + (buf) * 30720;                                  \
        uint32_t abase = bufb + (wb * 32 + lrow) * 80;                        \
        uint32_t bbase = bufb + 10240 + (wj * 16 + lrow) * 80;                \
        _Pragma("unroll")                                                     \
        for (int s = 0; s < 2; s++) {                                         \
            uint32_t koff = (uint32_t)((s * 8 + tg) * 4);                     \
            uint32_t ah[2][4], al[2][4];                                      \
            _Pragma("unroll")                                                 \
            for (int mt = 0; mt < 2; mt++) {                                  \
                uint32_t ad = abase + mt * 1280 + koff;                       \
                ah[mt][0] = lds32(ad);                                        \
                ah[mt][1] = lds32(ad + 640);                                  \
                ah[mt][2] = lds32(ad + 16);                                   \
                ah[mt][3] = lds32(ad + 656);                                  \
                al[mt][0] = lds32(ad + 5120);                                 \
                al[mt][1] = lds32(ad + 5760);                                 \
                al[mt][2] = lds32(ad + 5136);                                 \
                al[mt][3] = lds32(ad + 5776);                                 \
            }                                                                 \
            uint32_t bh[2][2][2], bl[2][2][2];                                \
            _Pragma("unroll")                                                 \
            for (int gl = 0; gl < 2; gl++)                                    \
                _Pragma("unroll")                                             \
                for (int nt = 0; nt < 2; nt++) {                              \
                    uint32_t bd = bbase + gl * 5120 + nt * 640 + koff;        \
                    bh[gl][nt][0] = lds32(bd);                                \
                    bh[gl][nt][1] = lds32(bd + 16);                           \
                    bl[gl][nt][0] = lds32(bd + 10240);                        \
                    bl[gl][nt][1] = lds32(bd + 10256);                        \
                }                                                             \
            _Pragma("unroll")                                                 \
            for (int mt = 0; mt < 2; mt++)                                    \
                _Pragma("unroll")                                             \
                for (int nt = 0; nt < 2; nt++)                                \
                    _Pragma("unroll")                                         \
                    for (int gl = 0; gl < 2; gl++) {                          \
                        mma_bf16(ACC[mt][nt][gl], ah[mt], bh[gl][nt]);        \
                        mma_bf16(ACC[mt][nt][gl], al[mt], bh[gl][nt]);        \
                        mma_bf16(ACC[mt][nt][gl], ah[mt], bl[gl][nt]);        \
                    }                                                         \
        }                                                                     \
    } while (0)

    // prologue
    FILL(0, 0, 0);
    // phase 0
    for (int cc = 0; cc < 6; cc++) {
        int buf = cc & 1;
        cp_wait0();
        __syncthreads();
        if (cc < 5)       FILL(buf ^ 1, 0, cc + 1);
        else              FILL(buf ^ 1, 1, 0);
        COMPUTE(acc0, buf);
    }
    // phase 1
    for (int cc = 0; cc < 6; cc++) {
        int buf = cc & 1;
        cp_wait0();
        __syncthreads();
        if (cc < 5) FILL(buf ^ 1, 1, cc + 1);
        COMPUTE(acc1, buf);
    }

    // ---- fused LSTM epilogue ------------------------------------------------
    #pragma unroll
    for (int mt = 0; mt < 2; mt++) {
        #pragma unroll
        for (int rr = 0; rr < 2; rr++) {
            int b = b0 + wb * 32 + mt * 16 + rr * 8 + lrow;
            #pragma unroll
            for (int nt = 0; nt < 2; nt++) {
                int jj = wj * 16 + nt * 8 + 2 * tg;   // 0..63 within tile
                size_t off = (size_t)b * NH + j0 + jj;
                float2 xv = *(const float2*)&x[off];
                float2 hv = *(const float2*)&h[off];
                float2 cv = *(const float2*)&c[off];
                float xa[2] = {xv.x, xv.y};
                float ha[2] = {hv.x, hv.y};
                float ca[2] = {cv.x, cv.y};
                float hn[2], cn[2];
                #pragma unroll
                for (int e = 0; e < 2; e++) {
                    int jc = jj + e;
                    int dr = rr * 2 + e;
                    float gi = acc0[mt][nt][0][dr];
                    float gf = acc0[mt][nt][1][dr];
                    float go = acc1[mt][nt][0][dr];
                    float gn = acc1[mt][nt][1][dr];
                    float base = epi[768 + jc] * xa[e] + epi[832 + jc] * ha[e];
                    float v0 = gi - xa[e] * epi[jc]       - ha[e] * epi[256 + jc] + epi[512 + jc] + base;
                    float v1 = gf - xa[e] * epi[64 + jc]  - ha[e] * epi[320 + jc] + epi[576 + jc] + base;
                    float v2 = go - xa[e] * epi[128 + jc] - ha[e] * epi[384 + jc] + epi[640 + jc] + base;
                    float v3 = gn - xa[e] * epi[192 + jc] - ha[e] * epi[448 + jc] + epi[704 + jc] + base;
                    float ig = sigm_f(v0);
                    float fg = sigm_f(v1);
                    float og = sigm_f(v2);
                    float ng = tanh_f(v3);
                    float cnx = fg * ca[e] + ig * ng;
                    cn[e] = cnx;
                    hn[e] = og * tanh_f(cnx);
                }
                *(float2*)&out[off] = make_float2(hn[0], hn[1]);
                *(float2*)&out[(size_t)NB * NH + off] = make_float2(cn[0], cn[1]);
            }
        }
    }
}

// ============================================================================
extern "C" void kernel_launch(void* const* d_in, const int* in_sizes, int n_in,
                              void* d_out, int out_size) {
    const float* x     = (const float*)d_in[0];
    const float* h     = (const float*)d_in[1];
    const float* c     = (const float*)d_in[2];
    const float* dia_x = (const float*)d_in[3];
    const float* dia_h = (const float*)d_in[4];
    const float* Ux    = (const float*)d_in[5];
    const float* Vx    = (const float*)d_in[6];
    const float* Uh0   = (const float*)d_in[7];
    const float* Vh0   = (const float*)d_in[8];
    const float* Uh1   = (const float*)d_in[9];
    const float* Vh1   = (const float*)d_in[10];
    const float* bx    = (const float*)d_in[11];
    const float* bh    = (const float*)d_in[12];
    float* out = (float*)d_out;

    cudaFuncSetAttribute(stage2_mma,
                         cudaFuncAttributeMaxDynamicSharedMemorySize, S2_DSMEM);

    pack_w_kernel<<<(4 * 1024 * 96 + 255) / 256, 256>>>(Vx, Vh0, Vh1);
    coef_kernel<<<16, 256>>>(Ux, Vx, Uh0, Vh0, bx, bh);
    stage1_kernel<<<dim3(64, 5), 256>>>(x, h, Ux, Uh0, Uh1);
    stage2_mma<<<dim3(16, 128), 256, S2_DSMEM>>>(x, h, c, dia_x, dia_h, out);
}

// round 8
// speedup vs baseline: 1.4794x; 1.1337x over previous
#include <cuda_runtime.h>
#include <cuda_bf16.h>
#include <cstdint>

// ============================================================================
// myVMLSTMCell fused low-rank LSTM — R8: stage2 mma.sync bf16, 2 CTAs/SM.
//   acc(phase0) spilled to smem between phases; B-frags loaded per (gl,nt);
//   __launch_bounds__(256,2). Everything else identical to R7.
// ============================================================================

typedef unsigned long long ull;

#define NB 8192
#define NH 1024

__device__ uint32_t g_Ah[NB*160];      // bf16 hi pairs [b][kpair]
__device__ uint32_t g_Al[NB*160];      // bf16 lo pairs
__device__ uint32_t g_Wh[4*1024*96];   // [gate][j][kpair]
__device__ uint32_t g_Wl[4*1024*96];
__device__ float g_cx[4*NH];
__device__ float g_ch[4*NH];
__device__ float g_cb[4*NH];

// ---- scalar helpers --------------------------------------------------------
__device__ __forceinline__ ull pk2(float lo, float hi) {
    ull r; asm("mov.b64 %0, {%1,%2};" : "=l"(r) : "f"(lo), "f"(hi)); return r;
}
__device__ __forceinline__ void upk2(ull v, float& lo, float& hi) {
    asm("mov.b64 {%0,%1}, %2;" : "=f"(lo), "=f"(hi) : "l"(v));
}
__device__ __forceinline__ void fma2(ull& d, ull a, ull b) {
    asm("fma.rn.f32x2 %0, %1, %2, %3;" : "=l"(d) : "l"(a), "l"(b), "l"(d));
}
__device__ __forceinline__ float sigm_f(float v) {
    return __fdividef(1.f, 1.f + __expf(-v));
}
__device__ __forceinline__ float tanh_f(float v) {
    return 1.f - __fdividef(2.f, 1.f + __expf(2.f * v));
}
__device__ __forceinline__ void bfsplit(float v, uint16_t& h, uint16_t& l) {
    __nv_bfloat16 bh = __float2bfloat16_rn(v);
    float r = v - __bfloat162float(bh);
    __nv_bfloat16 bl = __float2bfloat16_rn(r);
    h = __bfloat16_as_ushort(bh);
    l = __bfloat16_as_ushort(bl);
}
__device__ __forceinline__ uint32_t s2u(const void* p) {
    return (uint32_t)__cvta_generic_to_shared(p);
}
__device__ __forceinline__ void cp16(uint32_t dst, const void* src) {
    asm volatile("cp.async.cg.shared.global [%0], [%1], 16;\n"
                 :: "r"(dst), "l"(src));
}
__device__ __forceinline__ void cp_commit() {
    asm volatile("cp.async.commit_group;\n");
}
__device__ __forceinline__ void cp_wait0() {
    asm volatile("cp.async.wait_group 0;\n");
}
__device__ __forceinline__ uint32_t lds32(uint32_t a) {
    uint32_t v;
    asm volatile("ld.shared.b32 %0, [%1];" : "=r"(v) : "r"(a));
    return v;
}
__device__ __forceinline__ void mma_bf16(float* d, const uint32_t* a,
                                         const uint32_t* b) {
    asm volatile(
        "mma.sync.aligned.m16n8k16.row.col.f32.bf16.bf16.f32 "
        "{%0,%1,%2,%3}, {%4,%5,%6,%7}, {%8,%9}, {%0,%1,%2,%3};\n"
        : "+f"(d[0]), "+f"(d[1]), "+f"(d[2]), "+f"(d[3])
        : "r"(a[0]), "r"(a[1]), "r"(a[2]), "r"(a[3]), "r"(b[0]), "r"(b[1]));
}

// ============================================================================
// Kernel A1: pack split weights g_Wh/g_Wl[gate][j][kpair]
// ============================================================================
__global__ void pack_w_kernel(const float* __restrict__ Vx,
                              const float* __restrict__ Vh0,
                              const float* __restrict__ Vh1) {
    int idx = blockIdx.x * 256 + threadIdx.x;
    if (idx >= 4 * 1024 * 96) return;
    int kp  = idx % 96;
    int j   = (idx / 96) & 1023;
    int kap = idx / (96 * 1024);
    int g   = kap >> 1;
    int mh  = (((kap ^ 1) & 1) << 10) + j;
    uint16_t h[2], l[2];
    #pragma unroll
    for (int e = 0; e < 2; e++) {
        int kk = kp * 2 + e;
        float v;
        if (kk < 64)        v = Vx[(kap * NH + j) * 64 + kk];
        else if (kk < 128)  v = Vh0[g * 131072 + (kk - 64) * 2048 + mh];
        else                v = Vh1[g * 131072 + (kk - 128) * 2048 + mh];
        bfsplit(v, h[e], l[e]);
    }
    g_Wh[idx] = (uint32_t)h[0] | ((uint32_t)h[1] << 16);
    g_Wl[idx] = (uint32_t)l[0] | ((uint32_t)l[1] << 16);
}

// ============================================================================
// Kernel A2: coef_x, coef_h (permuted), combined bias
// ============================================================================
__global__ void coef_kernel(const float* __restrict__ Ux,
                            const float* __restrict__ Vx,
                            const float* __restrict__ Uh0,
                            const float* __restrict__ Vh0,
                            const float* __restrict__ bx,
                            const float* __restrict__ bh) {
    int idx = blockIdx.x * 256 + threadIdx.x;
    if (idx >= 4 * NH) return;
    int j = idx & 1023;
    int kap = idx >> 10;
    int g  = kap >> 1;
    int mh = (((kap ^ 1) & 1) << 10) + j;
    float sx = 0.f, sh = 0.f;
    #pragma unroll 8
    for (int r = 0; r < 64; r++) {
        sx += Ux[j * 64 + r] * Vx[(kap * NH + j) * 64 + r];
        sh += Uh0[j * 64 + r] * Vh0[g * 131072 + r * 2048 + mh];
    }
    g_cx[idx] = sx;
    g_ch[idx] = sh;
    g_cb[idx] = bx[(kap << 10) + j] + bh[((kap ^ 1) << 10) + j];
}

// ============================================================================
// Kernel B: stage-1 FFMA2 contractions -> g_Ah/g_Al (bf16-split pairs)
// ============================================================================
__global__ __launch_bounds__(256) void stage1_kernel(
        const float* __restrict__ x, const float* __restrict__ h,
        const float* __restrict__ Ux, const float* __restrict__ Uh0,
        const float* __restrict__ Uh1) {
    __shared__ float Xs[64 * 132];
    __shared__ float Ws[64 * 64];

    int cb = blockIdx.y;
    const float* Ap; const float* Wp;
    int K, outoff, aoff;
    if (cb == 0) {
        Ap = x; Wp = Ux; K = 1024; outoff = 0; aoff = 0;
    } else {
        int e = cb - 1;
        int g = e >> 1, i = e & 1;
        Ap = h; Wp = (i ? Uh1 : Uh0) + g * 512 * 64;
        K = 512; outoff = 64 + g * 128 + i * 64;
        aoff = ((g + i) & 1) * 512;
    }
    int tid = threadIdx.x, tx = tid & 31, ty = tid >> 5;
    int b0 = blockIdx.x * 128;

    ull acc[8][2];
    #pragma unroll
    for (int p = 0; p < 8; p++) { acc[p][0] = 0ull; acc[p][1] = 0ull; }

    for (int k0 = 0; k0 < K; k0 += 64) {
        #pragma unroll
        for (int i2 = 0; i2 < 8; i2++) {
            int idx = tid + i2 * 256;
            int r = idx >> 4, c4 = idx & 15;
            float4 v = *(const float4*)&Ap[(size_t)(b0 + r) * NH + aoff + k0 + c4 * 4];
            float vv[4] = {v.x, v.y, v.z, v.w};
            #pragma unroll
            for (int q = 0; q < 4; q++) {
                int kk = c4 * 4 + q;
                int swz = (kk >> 2) & 7;
                Xs[kk * 128 + (((r >> 2) ^ swz) << 2) + (r & 3)] = vv[q];
            }
        }
        #pragma unroll
        for (int i2 = 0; i2 < 4; i2++) {
            int idx = tid + i2 * 256;
            int kk = idx >> 4, n4 = idx & 15;
            *(float4*)&Ws[kk * 64 + n4 * 4] =
                *(const float4*)&Wp[(size_t)(k0 + kk) * 64 + n4 * 4];
        }
        __syncthreads();
        #pragma unroll 4
        for (int kk = 0; kk < 64; kk++) {
            float2 wv = *(const float2*)&Ws[kk * 64 + tx * 2];
            ull w0 = pk2(wv.x, wv.x), w1 = pk2(wv.y, wv.y);
            int swz = (kk >> 2) & 7;
            ull a[8];
            #pragma unroll
            for (int j = 0; j < 4; j++) {
                ulonglong2 av = *(const ulonglong2*)
                    &Xs[kk * 128 + (((ty * 4 + j) ^ swz) << 2)];
                a[2 * j] = av.x; a[2 * j + 1] = av.y;
            }
            #pragma unroll
            for (int p = 0; p < 8; p++) {
                fma2(acc[p][0], a[p], w0);
                fma2(acc[p][1], a[p], w1);
            }
        }
        __syncthreads();
    }

    int cw = (outoff >> 1) + tx;
    #pragma unroll
    for (int p = 0; p < 8; p++) {
        float lo0, hi0, lo1, hi1;
        upk2(acc[p][0], lo0, hi0);
        upk2(acc[p][1], lo1, hi1);
        int b = b0 + ty * 16 + p * 2;
        uint16_t h0, l0, h1, l1;
        bfsplit(lo0, h0, l0); bfsplit(lo1, h1, l1);
        g_Ah[(size_t)b * 160 + cw] = (uint32_t)h0 | ((uint32_t)h1 << 16);
        g_Al[(size_t)b * 160 + cw] = (uint32_t)l0 | ((uint32_t)l1 << 16);
        bfsplit(hi0, h0, l0); bfsplit(hi1, h1, l1);
        g_Ah[(size_t)(b + 1) * 160 + cw] = (uint32_t)h0 | ((uint32_t)h1 << 16);
        g_Al[(size_t)(b + 1) * 160 + cw] = (uint32_t)l0 | ((uint32_t)l1 << 16);
    }
}

// ============================================================================
// Kernel C: stage-2 bf16 mma.sync GEMM + fused LSTM epilogue (2 CTAs/SM)
//   dyn smem: 2 bufs x 30720 + 32768 acc-spill = 94208 B
//   spill layout [e][tid] stride 256 (conflict-free)
// ============================================================================
#define S2_DSMEM (2*30720 + 32768)

__global__ __launch_bounds__(256, 2)
void stage2_mma(const float* __restrict__ x, const float* __restrict__ h,
                const float* __restrict__ c, const float* __restrict__ dia_x,
                const float* __restrict__ dia_h, float* __restrict__ out) {
    extern __shared__ char dsm[];
    __shared__ float epi[896];   // cx[4][64] | ch | cb | dx[64] | dh[64]
    uint32_t smu = s2u(dsm);
    float* spill = (float*)(dsm + 61440);

    int tid = threadIdx.x;
    int lane = tid & 31, wid = tid >> 5;
    int tg = lane & 3, lrow = lane >> 2;
    int wb = wid >> 2, wj = wid & 3;
    int j0 = blockIdx.x * 64;
    int b0 = blockIdx.y * 64;

    for (int i = tid; i < 896; i += 256) {
        float v;
        if (i < 256)       v = g_cx[(i >> 6) * 1024 + j0 + (i & 63)];
        else if (i < 512)  { int q = i - 256; v = g_ch[(q >> 6) * 1024 + j0 + (q & 63)]; }
        else if (i < 768)  { int q = i - 512; v = g_cb[(q >> 6) * 1024 + j0 + (q & 63)]; }
        else if (i < 832)  v = dia_x[j0 + i - 768];
        else               v = dia_h[j0 + i - 832];
        epi[i] = v;
    }

    // ---- fill chunk (p, cc) into buffer buf ----
    #define FILL(buf, p, cc) do {                                             \
        int cbh = ((cc) < 2) ? (cc) * 16 : 64 * (p) + (cc) * 16;              \
        {                                                                     \
            int row = tid >> 2, q = tid & 3;                                  \
            uint32_t dst = smu + (buf) * 30720 + row * 80 + q * 16;           \
            size_t si = (size_t)(b0 + row) * 160 + cbh + q * 4;               \
            cp16(dst, &g_Ah[si]);                                             \
            cp16(dst + 5120, &g_Al[si]);                                      \
        }                                                                     \
        _Pragma("unroll")                                                     \
        for (int i2 = 0; i2 < 2; i2++) {                                      \
            int idx = tid + i2 * 256;                                         \
            int gl = idx >> 8, rem = idx & 255;                               \
            int n = rem >> 2, q = rem & 3;                                    \
            uint32_t dst = smu + (buf) * 30720 + 10240 +                      \
                           (gl * 64 + n) * 80 + q * 16;                       \
            size_t si = (size_t)((2 * (p) + gl) * 1024 + j0 + n) * 96 +       \
                        (cc) * 16 + q * 4;                                    \
            cp16(dst, &g_Wh[si]);                                             \
            cp16(dst + 10240, &g_Wl[si]);                                     \
        }                                                                     \
        cp_commit();                                                          \
    } while (0)

    // ---- compute one chunk: B frags loaded per (gl,nt) to cap live regs ----
    #define COMPUTE(ACC, buf) do {                                            \
        uint32_t bufb = smu + (buf) * 30720;                                  \
        uint32_t abase = bufb + (wb * 32 + lrow) * 80;                        \
        uint32_t bbase = bufb + 10240 + (wj * 16 + lrow) * 80;                \
        _Pragma("unroll")                                                     \
        for (int s = 0; s < 2; s++) {                                         \
            uint32_t koff = (uint32_t)((s * 8 + tg) * 4);                     \
            uint32_t ah[2][4], al[2][4];                                      \
            _Pragma("unroll")                                                 \
            for (int mt = 0; mt < 2; mt++) {                                  \
                uint32_t ad = abase + mt * 1280 + koff;                       \
                ah[mt][0] = lds32(ad);                                        \
                ah[mt][1] = lds32(ad + 640);                                  \
                ah[mt][2] = lds32(ad + 16);                                   \
                ah[mt][3] = lds32(ad + 656);                                  \
                al[mt][0] = lds32(ad + 5120);                                 \
                al[mt][1] = lds32(ad + 5760);                                 \
                al[mt][2] = lds32(ad + 5136);                                 \
                al[mt][3] = lds32(ad + 5776);                                 \
            }                                                                 \
            _Pragma("unroll")                                                 \
            for (int gl = 0; gl < 2; gl++)                                    \
                _Pragma("unroll")                                             \
                for (int nt = 0; nt < 2; nt++) {                              \
                    uint32_t bd = bbase + gl * 5120 + nt * 640 + koff;        \
                    uint32_t bh[2], bl[2];                                    \
                    bh[0] = lds32(bd);                                        \
                    bh[1] = lds32(bd + 16);                                   \
                    bl[0] = lds32(bd + 10240);                                \
                    bl[1] = lds32(bd + 10256);                                \
                    _Pragma("unroll")                                         \
                    for (int mt = 0; mt < 2; mt++) {                          \
                        mma_bf16(ACC[mt][nt][gl], ah[mt], bh);                \
                        mma_bf16(ACC[mt][nt][gl], al[mt], bh);                \
                        mma_bf16(ACC[mt][nt][gl], ah[mt], bl);                \
                    }                                                         \
                }                                                             \
        }                                                                     \
    } while (0)

    // ---------------- phase 0 (gates i,f) ----------------
    {
        float acc0[2][2][2][4];
        #pragma unroll
        for (int a1 = 0; a1 < 2; a1++)
            #pragma unroll
            for (int a2 = 0; a2 < 2; a2++)
                #pragma unroll
                for (int a3 = 0; a3 < 2; a3++)
                    #pragma unroll
                    for (int a4 = 0; a4 < 4; a4++) acc0[a1][a2][a3][a4] = 0.f;

        FILL(0, 0, 0);
        for (int cc = 0; cc < 6; cc++) {
            int buf = cc & 1;
            cp_wait0();
            __syncthreads();
            if (cc < 5) FILL(buf ^ 1, 0, cc + 1);
            else        FILL(buf ^ 1, 1, 0);
            COMPUTE(acc0, buf);
        }
        // spill acc0 -> smem [e][tid]
        #pragma unroll
        for (int mt = 0; mt < 2; mt++)
            #pragma unroll
            for (int nt = 0; nt < 2; nt++)
                #pragma unroll
                for (int gl = 0; gl < 2; gl++)
                    #pragma unroll
                    for (int dr = 0; dr < 4; dr++) {
                        int e = ((mt * 2 + nt) * 2 + gl) * 4 + dr;
                        spill[e * 256 + tid] = acc0[mt][nt][gl][dr];
                    }
    }

    // ---------------- phase 1 (gates o,n) ----------------
    float acc1[2][2][2][4];
    #pragma unroll
    for (int a1 = 0; a1 < 2; a1++)
        #pragma unroll
        for (int a2 = 0; a2 < 2; a2++)
            #pragma unroll
            for (int a3 = 0; a3 < 2; a3++)
                #pragma unroll
                for (int a4 = 0; a4 < 4; a4++) acc1[a1][a2][a3][a4] = 0.f;

    for (int cc = 0; cc < 6; cc++) {
        int buf = cc & 1;
        cp_wait0();
        __syncthreads();
        if (cc < 5) FILL(buf ^ 1, 1, cc + 1);
        COMPUTE(acc1, buf);
    }

    // ---- fused LSTM epilogue (acc0 read back from smem) ---------------------
    #pragma unroll
    for (int mt = 0; mt < 2; mt++) {
        #pragma unroll
        for (int rr = 0; rr < 2; rr++) {
            int b = b0 + wb * 32 + mt * 16 + rr * 8 + lrow;
            #pragma unroll
            for (int nt = 0; nt < 2; nt++) {
                int jj = wj * 16 + nt * 8 + 2 * tg;
                size_t off = (size_t)b * NH + j0 + jj;
                float2 xv = *(const float2*)&x[off];
                float2 hv = *(const float2*)&h[off];
                float2 cv = *(const float2*)&c[off];
                float xa[2] = {xv.x, xv.y};
                float ha[2] = {hv.x, hv.y};
                float ca[2] = {cv.x, cv.y};
                float hn[2], cn[2];
                #pragma unroll
                for (int e = 0; e < 2; e++) {
                    int jc = jj + e;
                    int dr = rr * 2 + e;
                    int eb = ((mt * 2 + nt) * 2) * 4 + dr;
                    float gi = spill[eb * 256 + tid];
                    float gf = spill[(eb + 4) * 256 + tid];
                    float go = acc1[mt][nt][0][dr];
                    float gn = acc1[mt][nt][1][dr];
                    float base = epi[768 + jc] * xa[e] + epi[832 + jc] * ha[e];
                    float v0 = gi - xa[e] * epi[jc]       - ha[e] * epi[256 + jc] + epi[512 + jc] + base;
                    float v1 = gf - xa[e] * epi[64 + jc]  - ha[e] * epi[320 + jc] + epi[576 + jc] + base;
                    float v2 = go - xa[e] * epi[128 + jc] - ha[e] * epi[384 + jc] + epi[640 + jc] + base;
                    float v3 = gn - xa[e] * epi[192 + jc] - ha[e] * epi[448 + jc] + epi[704 + jc] + base;
                    float ig = sigm_f(v0);
                    float fg = sigm_f(v1);
                    float og = sigm_f(v2);
                    float ng = tanh_f(v3);
                    float cnx = fg * ca[e] + ig * ng;
                    cn[e] = cnx;
                    hn[e] = og * tanh_f(cnx);
                }
                *(float2*)&out[off] = make_float2(hn[0], hn[1]);
                *(float2*)&out[(size_t)NB * NH + off] = make_float2(cn[0], cn[1]);
            }
        }
    }
}

// ============================================================================
extern "C" void kernel_launch(void* const* d_in, const int* in_sizes, int n_in,
                              void* d_out, int out_size) {
    const float* x     = (const float*)d_in[0];
    const float* h     = (const float*)d_in[1];
    const float* c     = (const float*)d_in[2];
    const float* dia_x = (const float*)d_in[3];
    const float* dia_h = (const float*)d_in[4];
    const float* Ux    = (const float*)d_in[5];
    const float* Vx    = (const float*)d_in[6];
    const float* Uh0   = (const float*)d_in[7];
    const float* Vh0   = (const float*)d_in[8];
    const float* Uh1   = (const float*)d_in[9];
    const float* Vh1   = (const float*)d_in[10];
    const float* bx    = (const float*)d_in[11];
    const float* bh    = (const float*)d_in[12];
    float* out = (float*)d_out;

    cudaFuncSetAttribute(stage2_mma,
                         cudaFuncAttributeMaxDynamicSharedMemorySize, S2_DSMEM);

    pack_w_kernel<<<(4 * 1024 * 96 + 255) / 256, 256>>>(Vx, Vh0, Vh1);
    coef_kernel<<<16, 256>>>(Ux, Vx, Uh0, Vh0, bx, bh);
    stage1_kernel<<<dim3(64, 5), 256>>>(x, h, Ux, Uh0, Uh1);
    stage2_mma<<<dim3(16, 128), 256, S2_DSMEM>>>(x, h, c, dia_x, dia_h, out);
}

// round 9
// speedup vs baseline: 2.0455x; 1.3826x over previous
#include <cuda_runtime.h>
#include <cuda_bf16.h>
#include <cstdint>

// ============================================================================
// myVMLSTMCell fused low-rank LSTM — R9: BOTH stages on mma.sync bf16 (2-split).
//   pack_w: stage2 weights [gate][j][96 kpairs] hi/lo.
//   pack_u: stage1 weights [cb][n][Kp kpairs] hi/lo (cb0=Ux Kp=512, cb1-4 Kp=256)
//   stage1_mma: 5 GEMMs (128b x 64n per CTA) -> g_Ah/g_Al bf16-split pairs.
//   stage2_mma: K=192 x 2 phases + fused LSTM epilogue (unchanged from R8).
// ============================================================================

typedef unsigned long long ull;

#define NB 8192
#define NH 1024

__device__ uint32_t g_Ah[NB*160];      // bf16 hi pairs [b][kpair]
__device__ uint32_t g_Al[NB*160];      // bf16 lo pairs
__device__ uint32_t g_Wh[4*1024*96];   // stage2 W [gate][j][kpair]
__device__ uint32_t g_Wl[4*1024*96];
__device__ uint32_t g_Uhi[98304];      // stage1 U: cb0 64n*512kp, cb1-4 64n*256kp
__device__ uint32_t g_Ulo[98304];
__device__ float g_cx[4*NH];
__device__ float g_ch[4*NH];
__device__ float g_cb[4*NH];

// ---- scalar helpers --------------------------------------------------------
__device__ __forceinline__ float sigm_f(float v) {
    return __fdividef(1.f, 1.f + __expf(-v));
}
__device__ __forceinline__ float tanh_f(float v) {
    return 1.f - __fdividef(2.f, 1.f + __expf(2.f * v));
}
__device__ __forceinline__ void bfsplit(float v, uint16_t& h, uint16_t& l) {
    __nv_bfloat16 bh = __float2bfloat16_rn(v);
    float r = v - __bfloat162float(bh);
    __nv_bfloat16 bl = __float2bfloat16_rn(r);
    h = __bfloat16_as_ushort(bh);
    l = __bfloat16_as_ushort(bl);
}
__device__ __forceinline__ uint32_t s2u(const void* p) {
    return (uint32_t)__cvta_generic_to_shared(p);
}
__device__ __forceinline__ void cp16(uint32_t dst, const void* src) {
    asm volatile("cp.async.cg.shared.global [%0], [%1], 16;\n"
                 :: "r"(dst), "l"(src));
}
__device__ __forceinline__ void cp_commit() {
    asm volatile("cp.async.commit_group;\n");
}
__device__ __forceinline__ void cp_wait0() {
    asm volatile("cp.async.wait_group 0;\n");
}
__device__ __forceinline__ uint32_t lds32(uint32_t a) {
    uint32_t v;
    asm volatile("ld.shared.b32 %0, [%1];" : "=r"(v) : "r"(a));
    return v;
}
__device__ __forceinline__ void sts64(uint32_t a, uint32_t v0, uint32_t v1) {
    asm volatile("st.shared.v2.b32 [%0], {%1,%2};" :: "r"(a), "r"(v0), "r"(v1));
}
__device__ __forceinline__ void mma_bf16(float* d, const uint32_t* a,
                                         const uint32_t* b) {
    asm volatile(
        "mma.sync.aligned.m16n8k16.row.col.f32.bf16.bf16.f32 "
        "{%0,%1,%2,%3}, {%4,%5,%6,%7}, {%8,%9}, {%0,%1,%2,%3};\n"
        : "+f"(d[0]), "+f"(d[1]), "+f"(d[2]), "+f"(d[3])
        : "r"(a[0]), "r"(a[1]), "r"(a[2]), "r"(a[3]), "r"(b[0]), "r"(b[1]));
}
__device__ __forceinline__ uint32_t pack_hi(float a, float b) {
    uint16_t ha, la, hb, lb;
    bfsplit(a, ha, la); bfsplit(b, hb, lb);
    return (uint32_t)ha | ((uint32_t)hb << 16);
}

// ============================================================================
// Kernel A1: pack stage2 split weights g_Wh/g_Wl[gate][j][kpair]
// ============================================================================
__global__ void pack_w_kernel(const float* __restrict__ Vx,
                              const float* __restrict__ Vh0,
                              const float* __restrict__ Vh1) {
    int idx = blockIdx.x * 256 + threadIdx.x;
    if (idx >= 4 * 1024 * 96) return;
    int kp  = idx % 96;
    int j   = (idx / 96) & 1023;
    int kap = idx / (96 * 1024);
    int g   = kap >> 1;
    int mh  = (((kap ^ 1) & 1) << 10) + j;
    uint16_t h[2], l[2];
    #pragma unroll
    for (int e = 0; e < 2; e++) {
        int kk = kp * 2 + e;
        float v;
        if (kk < 64)        v = Vx[(kap * NH + j) * 64 + kk];
        else if (kk < 128)  v = Vh0[g * 131072 + (kk - 64) * 2048 + mh];
        else                v = Vh1[g * 131072 + (kk - 128) * 2048 + mh];
        bfsplit(v, h[e], l[e]);
    }
    g_Wh[idx] = (uint32_t)h[0] | ((uint32_t)h[1] << 16);
    g_Wl[idx] = (uint32_t)l[0] | ((uint32_t)l[1] << 16);
}

// ============================================================================
// Kernel A1b: pack stage1 U weights, [n][kpair] per cb, hi/lo
//   layout: cb0 at 0 (Kp=512), cb e=1..4 at 32768+(e-1)*16384 (Kp=256)
// ============================================================================
__global__ void pack_u_kernel(const float* __restrict__ Ux,
                              const float* __restrict__ Uh0,
                              const float* __restrict__ Uh1) {
    int idx = blockIdx.x * 256 + threadIdx.x;
    if (idx >= 98304) return;
    const float* src;
    int n, kp;
    if (idx < 32768) {
        n = idx >> 9; kp = idx & 511;
        src = Ux;
    } else {
        int rem = idx - 32768;
        int e = rem >> 14;
        n = (rem >> 8) & 63; kp = rem & 255;
        int g = e >> 1, i = e & 1;
        src = (i ? Uh1 : Uh0) + g * 512 * 64;
    }
    uint16_t h[2], l[2];
    #pragma unroll
    for (int ee = 0; ee < 2; ee++)
        bfsplit(src[(2 * kp + ee) * 64 + n], h[ee], l[ee]);
    g_Uhi[idx] = (uint32_t)h[0] | ((uint32_t)h[1] << 16);
    g_Ulo[idx] = (uint32_t)l[0] | ((uint32_t)l[1] << 16);
}

// ============================================================================
// Kernel A2: coef_x, coef_h (permuted), combined bias
// ============================================================================
__global__ void coef_kernel(const float* __restrict__ Ux,
                            const float* __restrict__ Vx,
                            const float* __restrict__ Uh0,
                            const float* __restrict__ Vh0,
                            const float* __restrict__ bx,
                            const float* __restrict__ bh) {
    int idx = blockIdx.x * 256 + threadIdx.x;
    if (idx >= 4 * NH) return;
    int j = idx & 1023;
    int kap = idx >> 10;
    int g  = kap >> 1;
    int mh = (((kap ^ 1) & 1) << 10) + j;
    float sx = 0.f, sh = 0.f;
    #pragma unroll 8
    for (int r = 0; r < 64; r++) {
        sx += Ux[j * 64 + r] * Vx[(kap * NH + j) * 64 + r];
        sh += Uh0[j * 64 + r] * Vh0[g * 131072 + r * 2048 + mh];
    }
    g_cx[idx] = sx;
    g_ch[idx] = sh;
    g_cb[idx] = bx[(kap << 10) + j] + bh[((kap ^ 1) << 10) + j];
}

// ============================================================================
// Kernel B: stage1 on mma.sync — 5 GEMMs, CTA = 128b x 64n
//   smem per buf (30720B): A_hi [128r x 80B], A_lo (+10240),
//                          W_hi (+20480, 64r x 80B), W_lo (+25600)
//   warps: wb = wid>>1 (4 x 32b), wj = wid&1 (2 x 32n); acc[2mt][4nt][4]
// ============================================================================
#define S1_DSMEM (2*30720)

__global__ __launch_bounds__(256, 2)
void stage1_mma(const float* __restrict__ x, const float* __restrict__ h) {
    extern __shared__ char dsm[];
    uint32_t smu = s2u(dsm);

    int tid = threadIdx.x;
    int lane = tid & 31, wid = tid >> 5;
    int tg = lane & 3, lrow = lane >> 2;
    int wb = wid >> 1, wj = wid & 1;
    int b0 = blockIdx.x * 128;
    int cb = blockIdx.y;

    const float* Ap;
    int NC, Kp, uoff, aoff, outoff;
    if (cb == 0) {
        Ap = x; NC = 32; Kp = 512; uoff = 0; aoff = 0; outoff = 0;
    } else {
        int e = cb - 1;
        int g = e >> 1, i = e & 1;
        Ap = h; NC = 16; Kp = 256;
        uoff = 32768 + e * 16384;
        aoff = ((g + i) & 1) * 512;
        outoff = 64 + g * 128 + i * 64;
    }

    float4 pf[4];

    #define S1_LDG(cc) do {                                                   \
        int row = tid >> 1, cg = tid & 1;                                     \
        const float* src = &Ap[(size_t)(b0 + row) * NH + aoff +               \
                               (cc) * 32 + cg * 16];                          \
        pf[0] = *(const float4*)(src);                                        \
        pf[1] = *(const float4*)(src + 4);                                    \
        pf[2] = *(const float4*)(src + 8);                                    \
        pf[3] = *(const float4*)(src + 12);                                   \
    } while (0)

    #define S1_STS(buf) do {                                                  \
        int row = tid >> 1, cg = tid & 1;                                     \
        uint32_t ab = smu + (buf) * 30720 + row * 80 + cg * 32;               \
        _Pragma("unroll")                                                     \
        for (int q4 = 0; q4 < 4; q4++) {                                      \
            float f0 = pf[q4].x, f1 = pf[q4].y, f2 = pf[q4].z, f3 = pf[q4].w; \
            uint16_t h0, l0, h1, l1, h2, l2, h3, l3;                          \
            bfsplit(f0, h0, l0); bfsplit(f1, h1, l1);                         \
            bfsplit(f2, h2, l2); bfsplit(f3, h3, l3);                         \
            sts64(ab + q4 * 8,                                                \
                  (uint32_t)h0 | ((uint32_t)h1 << 16),                        \
                  (uint32_t)h2 | ((uint32_t)h3 << 16));                       \
            sts64(ab + 10240 + q4 * 8,                                        \
                  (uint32_t)l0 | ((uint32_t)l1 << 16),                        \
                  (uint32_t)l2 | ((uint32_t)l3 << 16));                       \
        }                                                                     \
    } while (0)

    #define S1_CPW(cc, buf) do {                                              \
        int n = tid >> 2, q = tid & 3;                                        \
        uint32_t dst = smu + (buf) * 30720 + 20480 + n * 80 + q * 16;         \
        size_t si = (size_t)uoff + (size_t)n * Kp + (cc) * 16 + q * 4;        \
        cp16(dst, &g_Uhi[si]);                                                \
        cp16(dst + 5120, &g_Ulo[si]);                                         \
        cp_commit();                                                          \
    } while (0)

    #define S1_COMPUTE(buf) do {                                              \
        uint32_t bufb = smu + (buf) * 30720;                                  \
        uint32_t abase = bufb + (wb * 32 + lrow) * 80;                        \
        uint32_t bbase = bufb + 20480 + (wj * 32 + lrow) * 80;                \
        _Pragma("unroll")                                                     \
        for (int s = 0; s < 2; s++) {                                         \
            uint32_t koff = (uint32_t)((s * 8 + tg) * 4);                     \
            uint32_t ah[2][4], al[2][4];                                      \
            _Pragma("unroll")                                                 \
            for (int mt = 0; mt < 2; mt++) {                                  \
                uint32_t ad = abase + mt * 1280 + koff;                       \
                ah[mt][0] = lds32(ad);                                        \
                ah[mt][1] = lds32(ad + 640);                                  \
                ah[mt][2] = lds32(ad + 16);                                   \
                ah[mt][3] = lds32(ad + 656);                                  \
                al[mt][0] = lds32(ad + 10240);                                \
                al[mt][1] = lds32(ad + 10880);                                \
                al[mt][2] = lds32(ad + 10256);                                \
                al[mt][3] = lds32(ad + 10896);                                \
            }                                                                 \
            _Pragma("unroll")                                                 \
            for (int nt = 0; nt < 4; nt++) {                                  \
                uint32_t bd = bbase + nt * 640 + koff;                        \
                uint32_t bh[2], bl[2];                                        \
                bh[0] = lds32(bd);                                            \
                bh[1] = lds32(bd + 16);                                       \
                bl[0] = lds32(bd + 5120);                                     \
                bl[1] = lds32(bd + 5136);                                     \
                _Pragma("unroll")                                             \
                for (int mt = 0; mt < 2; mt++) {                              \
                    mma_bf16(acc[mt][nt], ah[mt], bh);                        \
                    mma_bf16(acc[mt][nt], al[mt], bh);                        \
                    mma_bf16(acc[mt][nt], ah[mt], bl);                        \
                }                                                             \
            }                                                                 \
        }                                                                     \
    } while (0)

    float acc[2][4][4];
    #pragma unroll
    for (int a1 = 0; a1 < 2; a1++)
        #pragma unroll
        for (int a2 = 0; a2 < 4; a2++)
            #pragma unroll
            for (int a3 = 0; a3 < 4; a3++) acc[a1][a2][a3] = 0.f;

    // prologue
    S1_LDG(0);
    S1_CPW(0, 0);
    S1_STS(0);
    cp_wait0();
    __syncthreads();

    for (int cc = 0; cc < NC; cc++) {
        int buf = cc & 1;
        if (cc < NC - 1) {
            S1_CPW(cc + 1, buf ^ 1);
            S1_LDG(cc + 1);
        }
        S1_COMPUTE(buf);
        if (cc < NC - 1) {
            S1_STS(buf ^ 1);
            cp_wait0();
        }
        __syncthreads();
    }

    // epilogue: bfsplit accumulators -> g_Ah/g_Al
    int cwb = (outoff >> 1) + wj * 16;
    #pragma unroll
    for (int mt = 0; mt < 2; mt++) {
        int b1 = b0 + wb * 32 + mt * 16 + lrow;
        #pragma unroll
        for (int nt = 0; nt < 4; nt++) {
            int cw = cwb + nt * 4 + tg;
            float* d = acc[mt][nt];
            uint16_t h0, l0, h1, l1;
            bfsplit(d[0], h0, l0); bfsplit(d[1], h1, l1);
            g_Ah[(size_t)b1 * 160 + cw] = (uint32_t)h0 | ((uint32_t)h1 << 16);
            g_Al[(size_t)b1 * 160 + cw] = (uint32_t)l0 | ((uint32_t)l1 << 16);
            bfsplit(d[2], h0, l0); bfsplit(d[3], h1, l1);
            g_Ah[(size_t)(b1 + 8) * 160 + cw] = (uint32_t)h0 | ((uint32_t)h1 << 16);
            g_Al[(size_t)(b1 + 8) * 160 + cw] = (uint32_t)l0 | ((uint32_t)l1 << 16);
        }
    }
}

// ============================================================================
// Kernel C: stage-2 bf16 mma.sync GEMM + fused LSTM epilogue (2 CTAs/SM)
//   (unchanged from R8)
// ============================================================================
#define S2_DSMEM (2*30720 + 32768)

__global__ __launch_bounds__(256, 2)
void stage2_mma(const float* __restrict__ x, const float* __restrict__ h,
                const float* __restrict__ c, const float* __restrict__ dia_x,
                const float* __restrict__ dia_h, float* __restrict__ out) {
    extern __shared__ char dsm[];
    __shared__ float epi[896];
    uint32_t smu = s2u(dsm);
    float* spill = (float*)(dsm + 61440);

    int tid = threadIdx.x;
    int lane = tid & 31, wid = tid >> 5;
    int tg = lane & 3, lrow = lane >> 2;
    int wb = wid >> 2, wj = wid & 3;
    int j0 = blockIdx.x * 64;
    int b0 = blockIdx.y * 64;

    for (int i = tid; i < 896; i += 256) {
        float v;
        if (i < 256)       v = g_cx[(i >> 6) * 1024 + j0 + (i & 63)];
        else if (i < 512)  { int q = i - 256; v = g_ch[(q >> 6) * 1024 + j0 + (q & 63)]; }
        else if (i < 768)  { int q = i - 512; v = g_cb[(q >> 6) * 1024 + j0 + (q & 63)]; }
        else if (i < 832)  v = dia_x[j0 + i - 768];
        else               v = dia_h[j0 + i - 832];
        epi[i] = v;
    }

    #define FILL(buf, p, cc) do {                                             \
        int cbh = ((cc) < 2) ? (cc) * 16 : 64 * (p) + (cc) * 16;              \
        {                                                                     \
            int row = tid >> 2, q = tid & 3;                                  \
            uint32_t dst = smu + (buf) * 30720 + row * 80 + q * 16;           \
            size_t si = (size_t)(b0 + row) * 160 + cbh + q * 4;               \
            cp16(dst, &g_Ah[si]);                                             \
            cp16(dst + 5120, &g_Al[si]);                                      \
        }                                                                     \
        _Pragma("unroll")                                                     \
        for (int i2 = 0; i2 < 2; i2++) {                                      \
            int idx = tid + i2 * 256;                                         \
            int gl = idx >> 8, rem = idx & 255;                               \
            int n = rem >> 2, q = rem & 3;                                    \
            uint32_t dst = smu + (buf) * 30720 + 10240 +                      \
                           (gl * 64 + n) * 80 + q * 16;                       \
            size_t si = (size_t)((2 * (p) + gl) * 1024 + j0 + n) * 96 +       \
                        (cc) * 16 + q * 4;                                    \
            cp16(dst, &g_Wh[si]);                                             \
            cp16(dst + 10240, &g_Wl[si]);                                     \
        }                                                                     \
        cp_commit();                                                          \
    } while (0)

    #define COMPUTE(ACC, buf) do {                                            \
        uint32_t bufb = smu + (buf) * 30720;                                  \
        uint32_t abase = bufb + (wb * 32 + lrow) * 80;                        \
        uint32_t bbase = bufb + 10240 + (wj * 16 + lrow) * 80;                \
        _Pragma("unroll")                                                     \
        for (int s = 0; s < 2; s++) {                                         \
            uint32_t koff = (uint32_t)((s * 8 + tg) * 4);                     \
            uint32_t ah[2][4], al[2][4];                                      \
            _Pragma("unroll")                                                 \
            for (int mt = 0; mt < 2; mt++) {                                  \
                uint32_t ad = abase + mt * 1280 + koff;                       \
                ah[mt][0] = lds32(ad);                                        \
                ah[mt][1] = lds32(ad + 640);                                  \
                ah[mt][2] = lds32(ad + 16);                                   \
                ah[mt][3] = lds32(ad + 656);                                  \
                al[mt][0] = lds32(ad + 5120);                                 \
                al[mt][1] = lds32(ad + 5760);                                 \
                al[mt][2] = lds32(ad + 5136);                                 \
                al[mt][3] = lds32(ad + 5776);                                 \
            }                                                                 \
            _Pragma("unroll")                                                 \
            for (int gl = 0; gl < 2; gl++)                                    \
                _Pragma("unroll")                                             \
                for (int nt = 0; nt < 2; nt++) {                              \
                    uint32_t bd = bbase + gl * 5120 + nt * 640 + koff;        \
                    uint32_t bh[2], bl[2];                                    \
                    bh[0] = lds32(bd);                                        \
                    bh[1] = lds32(bd + 16);                                   \
                    bl[0] = lds32(bd + 10240);                                \
                    bl[1] = lds32(bd + 10256);                                \
                    _Pragma("unroll")                                         \
                    for (int mt = 0; mt < 2; mt++) {                          \
                        mma_bf16(ACC[mt][nt][gl], ah[mt], bh);                \
                        mma_bf16(ACC[mt][nt][gl], al[mt], bh);                \
                        mma_bf16(ACC[mt][nt][gl], ah[mt], bl);                \
                    }                                                         \
                }                                                             \
        }                                                                     \
    } while (0)

    // ---------------- phase 0 (gates i,f) ----------------
    {
        float acc0[2][2][2][4];
        #pragma unroll
        for (int a1 = 0; a1 < 2; a1++)
            #pragma unroll
            for (int a2 = 0; a2 < 2; a2++)
                #pragma unroll
                for (int a3 = 0; a3 < 2; a3++)
                    #pragma unroll
                    for (int a4 = 0; a4 < 4; a4++) acc0[a1][a2][a3][a4] = 0.f;

        FILL(0, 0, 0);
        for (int cc = 0; cc < 6; cc++) {
            int buf = cc & 1;
            cp_wait0();
            __syncthreads();
            if (cc < 5) FILL(buf ^ 1, 0, cc + 1);
            else        FILL(buf ^ 1, 1, 0);
            COMPUTE(acc0, buf);
        }
        #pragma unroll
        for (int mt = 0; mt < 2; mt++)
            #pragma unroll
            for (int nt = 0; nt < 2; nt++)
                #pragma unroll
                for (int gl = 0; gl < 2; gl++)
                    #pragma unroll
                    for (int dr = 0; dr < 4; dr++) {
                        int e = ((mt * 2 + nt) * 2 + gl) * 4 + dr;
                        spill[e * 256 + tid] = acc0[mt][nt][gl][dr];
                    }
    }

    // ---------------- phase 1 (gates o,n) ----------------
    float acc1[2][2][2][4];
    #pragma unroll
    for (int a1 = 0; a1 < 2; a1++)
        #pragma unroll
        for (int a2 = 0; a2 < 2; a2++)
            #pragma unroll
            for (int a3 = 0; a3 < 2; a3++)
                #pragma unroll
                for (int a4 = 0; a4 < 4; a4++) acc1[a1][a2][a3][a4] = 0.f;

    for (int cc = 0; cc < 6; cc++) {
        int buf = cc & 1;
        cp_wait0();
        __syncthreads();
        if (cc < 5) FILL(buf ^ 1, 1, cc + 1);
        COMPUTE(acc1, buf);
    }

    // ---- fused LSTM epilogue ------------------------------------------------
    #pragma unroll
    for (int mt = 0; mt < 2; mt++) {
        #pragma unroll
        for (int rr = 0; rr < 2; rr++) {
            int b = b0 + wb * 32 + mt * 16 + rr * 8 + lrow;
            #pragma unroll
            for (int nt = 0; nt < 2; nt++) {
                int jj = wj * 16 + nt * 8 + 2 * tg;
                size_t off = (size_t)b * NH + j0 + jj;
                float2 xv = *(const float2*)&x[off];
                float2 hv = *(const float2*)&h[off];
                float2 cv = *(const float2*)&c[off];
                float xa[2] = {xv.x, xv.y};
                float ha[2] = {hv.x, hv.y};
                float ca[2] = {cv.x, cv.y};
                float hn[2], cn[2];
                #pragma unroll
                for (int e = 0; e < 2; e++) {
                    int jc = jj + e;
                    int dr = rr * 2 + e;
                    int eb = ((mt * 2 + nt) * 2) * 4 + dr;
                    float gi = spill[eb * 256 + tid];
                    float gf = spill[(eb + 4) * 256 + tid];
                    float go = acc1[mt][nt][0][dr];
                    float gn = acc1[mt][nt][1][dr];
                    float base = epi[768 + jc] * xa[e] + epi[832 + jc] * ha[e];
                    float v0 = gi - xa[e] * epi[jc]       - ha[e] * epi[256 + jc] + epi[512 + jc] + base;
                    float v1 = gf - xa[e] * epi[64 + jc]  - ha[e] * epi[320 + jc] + epi[576 + jc] + base;
                    float v2 = go - xa[e] * epi[128 + jc] - ha[e] * epi[384 + jc] + epi[640 + jc] + base;
                    float v3 = gn - xa[e] * epi[192 + jc] - ha[e] * epi[448 + jc] + epi[704 + jc] + base;
                    float ig = sigm_f(v0);
                    float fg = sigm_f(v1);
                    float og = sigm_f(v2);
                    float ng = tanh_f(v3);
                    float cnx = fg * ca[e] + ig * ng;
                    cn[e] = cnx;
                    hn[e] = og * tanh_f(cnx);
                }
                *(float2*)&out[off] = make_float2(hn[0], hn[1]);
                *(float2*)&out[(size_t)NB * NH + off] = make_float2(cn[0], cn[1]);
            }
        }
    }
}

// ============================================================================
extern "C" void kernel_launch(void* const* d_in, const int* in_sizes, int n_in,
                              void* d_out, int out_size) {
    const float* x     = (const float*)d_in[0];
    const float* h     = (const float*)d_in[1];
    const float* c     = (const float*)d_in[2];
    const float* dia_x = (const float*)d_in[3];
    const float* dia_h = (const float*)d_in[4];
    const float* Ux    = (const float*)d_in[5];
    const float* Vx    = (const float*)d_in[6];
    const float* Uh0   = (const float*)d_in[7];
    const float* Vh0   = (const float*)d_in[8];
    const float* Uh1   = (const float*)d_in[9];
    const float* Vh1   = (const float*)d_in[10];
    const float* bx    = (const float*)d_in[11];
    const float* bh    = (const float*)d_in[12];
    float* out = (float*)d_out;

    cudaFuncSetAttribute(stage1_mma,
                         cudaFuncAttributeMaxDynamicSharedMemorySize, S1_DSMEM);
    cudaFuncSetAttribute(stage2_mma,
                         cudaFuncAttributeMaxDynamicSharedMemorySize, S2_DSMEM);

    pack_w_kernel<<<(4 * 1024 * 96 + 255) / 256, 256>>>(Vx, Vh0, Vh1);
    pack_u_kernel<<<384, 256>>>(Ux, Uh0, Uh1);
    coef_kernel<<<16, 256>>>(Ux, Vx, Uh0, Vh0, bx, bh);
    stage1_mma<<<dim3(64, 5), 256, S1_DSMEM>>>(x, h);
    stage2_mma<<<dim3(16, 128), 256, S2_DSMEM>>>(x, h, c, dia_x, dia_h, out);
}

// round 10
// speedup vs baseline: 2.4666x; 1.2059x over previous
#include <cuda_runtime.h>
#include <cuda_bf16.h>
#include <cstdint>

// ============================================================================
// myVMLSTMCell fused low-rank LSTM — R10: fragment-native layouts.
//   All intermediates stored in m16n8k16 MMA fragment order (16B/lane/tile):
//   g_Ah/g_Al [b16][k16(20)][lane]  (A frags, written by stage1 C-frags)
//   g_Wh/g_Wl [kap][n8][cc6][lane]  (B frags, both k16-steps per 16B)
//   g_Uhi/g_Ulo frag layout per cb region.
//   COMPUTE loops use LDS.128 only (16/chunk/warp vs 128 lds32 in R9).
// ============================================================================

typedef unsigned long long ull;

#define NB 8192
#define NH 1024

__device__ uint32_t g_Ah[512*20*32*4];   // A frags hi (5.24 MB)
__device__ uint32_t g_Al[512*20*32*4];
__device__ uint32_t g_Wh[4*128*6*32*4];  // stage2 B frags hi
__device__ uint32_t g_Wl[4*128*6*32*4];
__device__ uint32_t g_Uhi[24576*4];      // stage1 B frags hi
__device__ uint32_t g_Ulo[24576*4];
__device__ float g_cx[4*NH];
__device__ float g_ch[4*NH];
__device__ float g_cb[4*NH];

// ---- helpers ---------------------------------------------------------------
__device__ __forceinline__ float sigm_f(float v) {
    return __fdividef(1.f, 1.f + __expf(-v));
}
__device__ __forceinline__ float tanh_f(float v) {
    return 1.f - __fdividef(2.f, 1.f + __expf(2.f * v));
}
__device__ __forceinline__ void bfsplit(float v, uint16_t& h, uint16_t& l) {
    __nv_bfloat16 bh = __float2bfloat16_rn(v);
    float r = v - __bfloat162float(bh);
    __nv_bfloat16 bl = __float2bfloat16_rn(r);
    h = __bfloat16_as_ushort(bh);
    l = __bfloat16_as_ushort(bl);
}
__device__ __forceinline__ void packpair(float f0, float f1,
                                         uint32_t& hi, uint32_t& lo) {
    uint16_t h0, l0, h1, l1;
    bfsplit(f0, h0, l0); bfsplit(f1, h1, l1);
    hi = (uint32_t)h0 | ((uint32_t)h1 << 16);
    lo = (uint32_t)l0 | ((uint32_t)l1 << 16);
}
__device__ __forceinline__ uint32_t s2u(const void* p) {
    return (uint32_t)__cvta_generic_to_shared(p);
}
__device__ __forceinline__ void cp16(uint32_t dst, const void* src) {
    asm volatile("cp.async.cg.shared.global [%0], [%1], 16;\n"
                 :: "r"(dst), "l"(src));
}
__device__ __forceinline__ void cp_commit() {
    asm volatile("cp.async.commit_group;\n");
}
__device__ __forceinline__ void cp_wait0() {
    asm volatile("cp.async.wait_group 0;\n");
}
__device__ __forceinline__ void lds128(uint32_t* r, uint32_t a) {
    asm volatile("ld.shared.v4.b32 {%0,%1,%2,%3}, [%4];"
                 : "=r"(r[0]), "=r"(r[1]), "=r"(r[2]), "=r"(r[3]) : "r"(a));
}
__device__ __forceinline__ void sts32(uint32_t a, uint32_t v) {
    asm volatile("st.shared.b32 [%0], %1;" :: "r"(a), "r"(v));
}
__device__ __forceinline__ void mma_bf16(float* d, const uint32_t* a,
                                         const uint32_t* b) {
    asm volatile(
        "mma.sync.aligned.m16n8k16.row.col.f32.bf16.bf16.f32 "
        "{%0,%1,%2,%3}, {%4,%5,%6,%7}, {%8,%9}, {%0,%1,%2,%3};\n"
        : "+f"(d[0]), "+f"(d[1]), "+f"(d[2]), "+f"(d[3])
        : "r"(a[0]), "r"(a[1]), "r"(a[2]), "r"(a[3]), "r"(b[0]), "r"(b[1]));
}

// ============================================================================
// pack_w: stage2 B frags. grid (16 jblk, 4 kap), 256 thr, 48KB smem staging.
//   frag[kap][n8(128)][cc(6)][lane] = {kp=cc*16+tg, +4, +8, +12} for j-col.
// ============================================================================
__global__ void pack_w_kernel(const float* __restrict__ Vx,
                              const float* __restrict__ Vh0,
                              const float* __restrict__ Vh1) {
    __shared__ float V[192][64];
    int tid = threadIdx.x;
    int jblk = blockIdx.x, kap = blockIdx.y;
    int g = kap >> 1;
    int mh0 = (((kap ^ 1) & 1) << 10) + jblk * 64;

    // stage Vx rows (kk 0..63): contiguous in kk per j
    #pragma unroll
    for (int i = 0; i < 4; i++) {
        int idx = tid + i * 256;             // 1024 f4
        int jl = idx >> 4, kq = idx & 15;
        float4 v = *(const float4*)
            &Vx[((size_t)(kap * NH + jblk * 64 + jl)) * 64 + kq * 4];
        V[kq * 4 + 0][jl] = v.x;
        V[kq * 4 + 1][jl] = v.y;
        V[kq * 4 + 2][jl] = v.z;
        V[kq * 4 + 3][jl] = v.w;
    }
    // stage Vh rows (kk 64..191): contiguous in j
    #pragma unroll
    for (int i = 0; i < 8; i++) {
        int idx = tid + i * 256;             // 2048 f4
        int kkr = idx >> 4, jq = idx & 15;
        const float* src = (kkr < 64)
            ? &Vh0[(size_t)g * 131072 + kkr * 2048 + mh0]
            : &Vh1[(size_t)g * 131072 + (kkr - 64) * 2048 + mh0];
        *(float4*)&V[64 + kkr][jq * 4] = *(const float4*)&src[jq * 4];
    }
    __syncthreads();

    // emit frags
    #pragma unroll
    for (int i = 0; i < 6; i++) {
        int idx = tid + i * 256;             // 1536 frags
        int n8l = idx / 192, rem = idx % 192;
        int cc = rem >> 5, lane = rem & 31;
        int jl = n8l * 8 + (lane >> 2), tg = lane & 3;
        uint32_t hi[4], lo[4];
        #pragma unroll
        for (int t = 0; t < 4; t++) {
            int kk = 2 * (cc * 16 + tg + t * 4);
            packpair(V[kk][jl], V[kk + 1][jl], hi[t], lo[t]);
        }
        size_t fo = (((size_t)kap * 128 + jblk * 8 + n8l) * 6 + cc) * 32 + lane;
        *(uint4*)&g_Wh[fo * 4] = make_uint4(hi[0], hi[1], hi[2], hi[3]);
        *(uint4*)&g_Wl[fo * 4] = make_uint4(lo[0], lo[1], lo[2], lo[3]);
    }
}

// ============================================================================
// pack_u: stage1 B frags. 24576 frags: cb0 [n8 8][cc 32][lane], e [8][16][32].
// ============================================================================
__global__ void pack_u_kernel(const float* __restrict__ Ux,
                              const float* __restrict__ Uh0,
                              const float* __restrict__ Uh1) {
    int idx = blockIdx.x * 256 + threadIdx.x;
    if (idx >= 24576) return;
    const float* src;
    int lane, tg, n, cc;
    if (idx < 8192) {
        int n8 = idx >> 10; cc = (idx >> 5) & 31; lane = idx & 31;
        n = n8 * 8 + (lane >> 2);
        src = Ux;
    } else {
        int rem = idx - 8192;
        int e = rem >> 12;
        int n8 = (rem >> 9) & 7; cc = (rem >> 5) & 15; lane = rem & 31;
        n = n8 * 8 + (lane >> 2);
        src = ((e & 1) ? Uh1 : Uh0) + (e >> 1) * 512 * 64;
    }
    tg = lane & 3;
    uint32_t hi[4], lo[4];
    #pragma unroll
    for (int t = 0; t < 4; t++) {
        int kp = cc * 16 + tg + t * 4;
        packpair(src[(size_t)(2 * kp) * 64 + n],
                 src[(size_t)(2 * kp + 1) * 64 + n], hi[t], lo[t]);
    }
    *(uint4*)&g_Uhi[(size_t)idx * 4] = make_uint4(hi[0], hi[1], hi[2], hi[3]);
    *(uint4*)&g_Ulo[(size_t)idx * 4] = make_uint4(lo[0], lo[1], lo[2], lo[3]);
}

// ============================================================================
// coef: coef_x, coef_h (permuted), combined bias
// ============================================================================
__global__ void coef_kernel(const float* __restrict__ Ux,
                            const float* __restrict__ Vx,
                            const float* __restrict__ Uh0,
                            const float* __restrict__ Vh0,
                            const float* __restrict__ bx,
                            const float* __restrict__ bh) {
    int idx = blockIdx.x * 256 + threadIdx.x;
    if (idx >= 4 * NH) return;
    int j = idx & 1023;
    int kap = idx >> 10;
    int g  = kap >> 1;
    int mh = (((kap ^ 1) & 1) << 10) + j;
    float sx = 0.f, sh = 0.f;
    #pragma unroll 8
    for (int r = 0; r < 64; r++) {
        sx += Ux[j * 64 + r] * Vx[(kap * NH + j) * 64 + r];
        sh += Uh0[j * 64 + r] * Vh0[g * 131072 + r * 2048 + mh];
    }
    g_cx[idx] = sx;
    g_ch[idx] = sh;
    g_cb[idx] = bx[(kap << 10) + j] + bh[((kap ^ 1) << 10) + j];
}

// ============================================================================
// stage1_mma: 5 GEMMs, CTA = 128b x 64n, frag smem.
//   buf (24576B): A_hi[0,8K) A_lo[8K,16K) W_hi[16K,20K) W_lo[20K,24K)
//   warps: wb=wid>>1 (4x32b), wj=wid&1 (2x32n)
// ============================================================================
#define S1_DSMEM (2*24576)

__global__ __launch_bounds__(256, 2)
void stage1_mma(const float* __restrict__ x, const float* __restrict__ h) {
    extern __shared__ char dsm[];
    uint32_t smu = s2u(dsm);

    int tid = threadIdx.x;
    int lane = tid & 31, wid = tid >> 5;
    int tg = lane & 3, lrow = lane >> 2;
    int wb = wid >> 1, wj = wid & 1;
    int b0 = blockIdx.x * 128;
    int cb = blockIdx.y;

    const float* Ap;
    int NC, NCC, ufrag, aoff, outoff;
    if (cb == 0) {
        Ap = x; NC = 32; NCC = 32; ufrag = 0; aoff = 0; outoff = 0;
    } else {
        int e = cb - 1;
        int g = e >> 1, i = e & 1;
        Ap = h; NC = 16; NCC = 16;
        ufrag = 8192 + e * 4096;
        aoff = ((g + i) & 1) * 512;
        outoff = 64 + g * 128 + i * 64;
    }

    float4 pf[4];
    int arow = tid >> 1, acg = tid & 1;

    #define S1_LDG(cc) do {                                                   \
        const float* src = &Ap[(size_t)(b0 + arow) * NH + aoff +              \
                               (cc) * 32 + acg * 16];                         \
        pf[0] = *(const float4*)(src);                                        \
        pf[1] = *(const float4*)(src + 4);                                    \
        pf[2] = *(const float4*)(src + 8);                                    \
        pf[3] = *(const float4*)(src + 12);                                   \
    } while (0)

    // frag layout write: lane=(r&7)*4+(q&3), slot=((q>>2)&1)*2+((r>>3)&1)
    #define S1_STS(buf) do {                                                  \
        uint32_t bufb = smu + (buf) * 24576;                                  \
        const float* pff = (const float*)pf;                                  \
        uint32_t fb = bufb + (((arow >> 4) * 2 + acg) * 32) * 16;             \
        _Pragma("unroll")                                                     \
        for (int q = 0; q < 8; q++) {                                         \
            uint32_t hi, lo;                                                  \
            packpair(pff[2 * q], pff[2 * q + 1], hi, lo);                     \
            uint32_t lt = ((arow & 7) << 2) + (q & 3);                        \
            uint32_t sl = ((q >> 2) & 1) * 2 + ((arow >> 3) & 1);             \
            uint32_t ad = fb + lt * 16 + sl * 4;                              \
            sts32(ad, hi);                                                    \
            sts32(ad + 8192, lo);                                             \
        }                                                                     \
    } while (0)

    #define S1_CPW(cc, buf) do {                                              \
        int n8 = tid >> 5, ln = tid & 31;                                     \
        uint32_t dst = smu + (buf) * 24576 + 16384 + (n8 * 32 + ln) * 16;     \
        size_t fo = (size_t)(ufrag + (n8 * NCC + (cc)) * 32 + ln) * 4;        \
        cp16(dst, &g_Uhi[fo]);                                                \
        cp16(dst + 4096, &g_Ulo[fo]);                                         \
        cp_commit();                                                          \
    } while (0)

    #define S1_COMPUTE(buf) do {                                              \
        uint32_t bufb = smu + (buf) * 24576;                                  \
        uint32_t bh[4][4], bl[4][4];                                          \
        _Pragma("unroll")                                                     \
        for (int nt = 0; nt < 4; nt++) {                                      \
            uint32_t ba = bufb + 16384 + (((wj * 4 + nt) * 32) + lane) * 16;  \
            lds128(bh[nt], ba);                                               \
            lds128(bl[nt], ba + 4096);                                        \
        }                                                                     \
        _Pragma("unroll")                                                     \
        for (int s = 0; s < 2; s++) {                                         \
            uint32_t ah[2][4], al[2][4];                                      \
            _Pragma("unroll")                                                 \
            for (int mt = 0; mt < 2; mt++) {                                  \
                uint32_t aa = bufb +                                          \
                    ((((wb * 2 + mt) * 2 + s) * 32) + lane) * 16;             \
                lds128(ah[mt], aa);                                           \
                lds128(al[mt], aa + 8192);                                    \
            }                                                                 \
            _Pragma("unroll")                                                 \
            for (int nt = 0; nt < 4; nt++) {                                  \
                uint32_t b2h[2] = {bh[nt][s * 2], bh[nt][s * 2 + 1]};         \
                uint32_t b2l[2] = {bl[nt][s * 2], bl[nt][s * 2 + 1]};         \
                _Pragma("unroll")                                             \
                for (int mt = 0; mt < 2; mt++) {                              \
                    mma_bf16(acc[mt][nt], ah[mt], b2h);                       \
                    mma_bf16(acc[mt][nt], al[mt], b2h);                       \
                    mma_bf16(acc[mt][nt], ah[mt], b2l);                       \
                }                                                             \
            }                                                                 \
        }                                                                     \
    } while (0)

    float acc[2][4][4];
    #pragma unroll
    for (int a1 = 0; a1 < 2; a1++)
        #pragma unroll
        for (int a2 = 0; a2 < 4; a2++)
            #pragma unroll
            for (int a3 = 0; a3 < 4; a3++) acc[a1][a2][a3] = 0.f;

    S1_LDG(0);
    S1_CPW(0, 0);
    S1_STS(0);
    cp_wait0();
    __syncthreads();

    for (int cc = 0; cc < NC; cc++) {
        int buf = cc & 1;
        if (cc < NC - 1) {
            S1_CPW(cc + 1, buf ^ 1);
            S1_LDG(cc + 1);
        }
        S1_COMPUTE(buf);
        if (cc < NC - 1) {
            S1_STS(buf ^ 1);
            cp_wait0();
        }
        __syncthreads();
    }

    // epilogue: C-frags -> g_Ah/g_Al fragment layout, 2 STG.128 per (mt,ntp)
    #pragma unroll
    for (int mt = 0; mt < 2; mt++) {
        int b16g = (b0 + wb * 32 + mt * 16) >> 4;
        #pragma unroll
        for (int ntp = 0; ntp < 2; ntp++) {
            int k16g = (outoff >> 4) + wj * 2 + ntp;
            uint32_t hi[4], lo[4];
            packpair(acc[mt][2 * ntp][0],     acc[mt][2 * ntp][1],     hi[0], lo[0]);
            packpair(acc[mt][2 * ntp][2],     acc[mt][2 * ntp][3],     hi[1], lo[1]);
            packpair(acc[mt][2 * ntp + 1][0], acc[mt][2 * ntp + 1][1], hi[2], lo[2]);
            packpair(acc[mt][2 * ntp + 1][2], acc[mt][2 * ntp + 1][3], hi[3], lo[3]);
            size_t fo = ((size_t)b16g * 20 + k16g) * 32 + lane;
            *(uint4*)&g_Ah[fo * 4] = make_uint4(hi[0], hi[1], hi[2], hi[3]);
            *(uint4*)&g_Al[fo * 4] = make_uint4(lo[0], lo[1], lo[2], lo[3]);
        }
    }
}

// ============================================================================
// stage2_mma: K=192 x 2 phases + fused LSTM epilogue (2 CTAs/SM).
//   buf (24576B): A_hi[0,4K) A_lo[4K,8K) W_hi[8K,16K) W_lo[16K,24K)
//   dyn smem: 2 bufs + 32KB acc spill = 81920 B
// ============================================================================
#define S2_DSMEM (2*24576 + 32768)

__global__ __launch_bounds__(256, 2)
void stage2_mma(const float* __restrict__ x, const float* __restrict__ h,
                const float* __restrict__ c, const float* __restrict__ dia_x,
                const float* __restrict__ dia_h, float* __restrict__ out) {
    extern __shared__ char dsm[];
    __shared__ float epi[896];
    uint32_t smu = s2u(dsm);
    float* spill = (float*)(dsm + 49152);

    int tid = threadIdx.x;
    int lane = tid & 31, wid = tid >> 5;
    int tg = lane & 3, lrow = lane >> 2;
    int wb = wid >> 2, wj = wid & 3;
    int j0 = blockIdx.x * 64;
    int b0 = blockIdx.y * 64;
    int b16base = b0 >> 4;
    int n8base = j0 >> 3;

    for (int i = tid; i < 896; i += 256) {
        float v;
        if (i < 256)       v = g_cx[(i >> 6) * 1024 + j0 + (i & 63)];
        else if (i < 512)  { int q = i - 256; v = g_ch[(q >> 6) * 1024 + j0 + (q & 63)]; }
        else if (i < 768)  { int q = i - 512; v = g_cb[(q >> 6) * 1024 + j0 + (q & 63)]; }
        else if (i < 832)  v = dia_x[j0 + i - 768];
        else               v = dia_h[j0 + i - 832];
        epi[i] = v;
    }

    #define FILL(buf, p, cc) do {                                             \
        uint32_t bufb = smu + (buf) * 24576;                                  \
        int k16base = ((cc) < 2) ? (cc) * 2 : (p) * 8 + (cc) * 2;             \
        {                                                                     \
            int b16l = tid >> 6, k16l = (tid >> 5) & 1, ln = tid & 31;        \
            size_t fo = (size_t)(((b16base + b16l) * 20 + k16base + k16l)     \
                                 * 32 + ln) * 4;                              \
            uint32_t dst = bufb + ((b16l * 2 + k16l) * 32 + ln) * 16;         \
            cp16(dst, &g_Ah[fo]);                                             \
            cp16(dst + 4096, &g_Al[fo]);                                      \
        }                                                                     \
        _Pragma("unroll")                                                     \
        for (int i2 = 0; i2 < 2; i2++) {                                      \
            int idx = tid + i2 * 256;                                         \
            int gl = idx >> 8, n8 = (idx >> 5) & 7, ln = idx & 31;            \
            size_t fo = (size_t)((((2 * (p) + gl) * 128 + n8base + n8) * 6    \
                                  + (cc)) * 32 + ln) * 4;                     \
            uint32_t dst = bufb + 8192 + ((gl * 8 + n8) * 32 + ln) * 16;      \
            cp16(dst, &g_Wh[fo]);                                             \
            cp16(dst + 8192, &g_Wl[fo]);                                      \
        }                                                                     \
        cp_commit();                                                          \
    } while (0)

    #define COMPUTE(ACC, buf) do {                                            \
        uint32_t bufb = smu + (buf) * 24576;                                  \
        uint32_t bh[2][2][4], bl[2][2][4];                                    \
        _Pragma("unroll")                                                     \
        for (int gl = 0; gl < 2; gl++)                                        \
            _Pragma("unroll")                                                 \
            for (int nt = 0; nt < 2; nt++) {                                  \
                uint32_t ba = bufb + 8192 +                                   \
                    ((gl * 8 + wj * 2 + nt) * 32 + lane) * 16;                \
                lds128(bh[gl][nt], ba);                                       \
                lds128(bl[gl][nt], ba + 8192);                                \
            }                                                                 \
        _Pragma("unroll")                                                     \
        for (int s = 0; s < 2; s++) {                                         \
            uint32_t ah[2][4], al[2][4];                                      \
            _Pragma("unroll")                                                 \
            for (int mt = 0; mt < 2; mt++) {                                  \
                uint32_t aa = bufb +                                          \
                    (((wb * 2 + mt) * 2 + s) * 32 + lane) * 16;               \
                lds128(ah[mt], aa);                                           \
                lds128(al[mt], aa + 4096);                                    \
            }                                                                 \
            _Pragma("unroll")                                                 \
            for (int gl = 0; gl < 2; gl++)                                    \
                _Pragma("unroll")                                             \
                for (int nt = 0; nt < 2; nt++) {                              \
                    uint32_t b2h[2] = {bh[gl][nt][s * 2], bh[gl][nt][s * 2 + 1]}; \
                    uint32_t b2l[2] = {bl[gl][nt][s * 2], bl[gl][nt][s * 2 + 1]}; \
                    _Pragma("unroll")                                         \
                    for (int mt = 0; mt < 2; mt++) {                          \
                        mma_bf16(ACC[mt][nt][gl], ah[mt], b2h);               \
                        mma_bf16(ACC[mt][nt][gl], al[mt], b2h);               \
                        mma_bf16(ACC[mt][nt][gl], ah[mt], b2l);               \
                    }                                                         \
                }                                                             \
        }                                                                     \
    } while (0)

    // ---------------- phase 0 (gates i,f) ----------------
    {
        float acc0[2][2][2][4];
        #pragma unroll
        for (int a1 = 0; a1 < 2; a1++)
            #pragma unroll
            for (int a2 = 0; a2 < 2; a2++)
                #pragma unroll
                for (int a3 = 0; a3 < 2; a3++)
                    #pragma unroll
                    for (int a4 = 0; a4 < 4; a4++) acc0[a1][a2][a3][a4] = 0.f;

        FILL(0, 0, 0);
        for (int cc = 0; cc < 6; cc++) {
            int buf = cc & 1;
            cp_wait0();
            __syncthreads();
            if (cc < 5) FILL(buf ^ 1, 0, cc + 1);
            else        FILL(buf ^ 1, 1, 0);
            COMPUTE(acc0, buf);
        }
        #pragma unroll
        for (int mt = 0; mt < 2; mt++)
            #pragma unroll
            for (int nt = 0; nt < 2; nt++)
                #pragma unroll
                for (int gl = 0; gl < 2; gl++)
                    #pragma unroll
                    for (int dr = 0; dr < 4; dr++) {
                        int e = ((mt * 2 + nt) * 2 + gl) * 4 + dr;
                        spill[e * 256 + tid] = acc0[mt][nt][gl][dr];
                    }
    }

    // ---------------- phase 1 (gates o,n) ----------------
    float acc1[2][2][2][4];
    #pragma unroll
    for (int a1 = 0; a1 < 2; a1++)
        #pragma unroll
        for (int a2 = 0; a2 < 2; a2++)
            #pragma unroll
            for (int a3 = 0; a3 < 2; a3++)
                #pragma unroll
                for (int a4 = 0; a4 < 4; a4++) acc1[a1][a2][a3][a4] = 0.f;

    for (int cc = 0; cc < 6; cc++) {
        int buf = cc & 1;
        cp_wait0();
        __syncthreads();
        if (cc < 5) FILL(buf ^ 1, 1, cc + 1);
        COMPUTE(acc1, buf);
    }

    // ---- fused LSTM epilogue ------------------------------------------------
    #pragma unroll
    for (int mt = 0; mt < 2; mt++) {
        #pragma unroll
        for (int rr = 0; rr < 2; rr++) {
            int b = b0 + wb * 32 + mt * 16 + rr * 8 + lrow;
            #pragma unroll
            for (int nt = 0; nt < 2; nt++) {
                int jj = wj * 16 + nt * 8 + 2 * tg;
                size_t off = (size_t)b * NH + j0 + jj;
                float2 xv = *(const float2*)&x[off];
                float2 hv = *(const float2*)&h[off];
                float2 cv = *(const float2*)&c[off];
                float xa[2] = {xv.x, xv.y};
                float ha[2] = {hv.x, hv.y};
                float ca[2] = {cv.x, cv.y};
                float hn[2], cn[2];
                #pragma unroll
                for (int e = 0; e < 2; e++) {
                    int jc = jj + e;
                    int dr = rr * 2 + e;
                    int eb = ((mt * 2 + nt) * 2) * 4 + dr;
                    float gi = spill[eb * 256 + tid];
                    float gf = spill[(eb + 4) * 256 + tid];
                    float go = acc1[mt][nt][0][dr];
                    float gn = acc1[mt][nt][1][dr];
                    float base = epi[768 + jc] * xa[e] + epi[832 + jc] * ha[e];
                    float v0 = gi - xa[e] * epi[jc]       - ha[e] * epi[256 + jc] + epi[512 + jc] + base;
                    float v1 = gf - xa[e] * epi[64 + jc]  - ha[e] * epi[320 + jc] + epi[576 + jc] + base;
                    float v2 = go - xa[e] * epi[128 + jc] - ha[e] * epi[384 + jc] + epi[640 + jc] + base;
                    float v3 = gn - xa[e] * epi[192 + jc] - ha[e] * epi[448 + jc] + epi[704 + jc] + base;
                    float ig = sigm_f(v0);
                    float fg = sigm_f(v1);
                    float og = sigm_f(v2);
                    float ng = tanh_f(v3);
                    float cnx = fg * ca[e] + ig * ng;
                    cn[e] = cnx;
                    hn[e] = og * tanh_f(cnx);
                }
                *(float2*)&out[off] = make_float2(hn[0], hn[1]);
                *(float2*)&out[(size_t)NB * NH + off] = make_float2(cn[0], cn[1]);
            }
        }
    }
}

// ============================================================================
extern "C" void kernel_launch(void* const* d_in, const int* in_sizes, int n_in,
                              void* d_out, int out_size) {
    const float* x     = (const float*)d_in[0];
    const float* h     = (const float*)d_in[1];
    const float* c     = (const float*)d_in[2];
    const float* dia_x = (const float*)d_in[3];
    const float* dia_h = (const float*)d_in[4];
    const float* Ux    = (const float*)d_in[5];
    const float* Vx    = (const float*)d_in[6];
    const float* Uh0   = (const float*)d_in[7];
    const float* Vh0   = (const float*)d_in[8];
    const float* Uh1   = (const float*)d_in[9];
    const float* Vh1   = (const float*)d_in[10];
    const float* bx    = (const float*)d_in[11];
    const float* bh    = (const float*)d_in[12];
    float* out = (float*)d_out;

    cudaFuncSetAttribute(stage1_mma,
                         cudaFuncAttributeMaxDynamicSharedMemorySize, S1_DSMEM);
    cudaFuncSetAttribute(stage2_mma,
                         cudaFuncAttributeMaxDynamicSharedMemorySize, S2_DSMEM);

    pack_w_kernel<<<dim3(16, 4), 256>>>(Vx, Vh0, Vh1);
    pack_u_kernel<<<96, 256>>>(Ux, Uh0, Uh1);
    coef_kernel<<<16, 256>>>(Ux, Vx, Uh0, Vh0, bx, bh);
    stage1_mma<<<dim3(64, 5), 256, S1_DSMEM>>>(x, h);
    stage2_mma<<<dim3(16, 128), 256, S2_DSMEM>>>(x, h, c, dia_x, dia_h, out);
}

// round 11
// speedup vs baseline: 2.5282x; 1.0250x over previous
#include <cuda_runtime.h>
#include <cuda_bf16.h>
#include <cstdint>

// ============================================================================
// myVMLSTMCell fused low-rank LSTM — R11:
//   stage1: conflict-free frag STS (lane' = tg*8+lrow, slot rotated by 2*(tile&1))
//   stage2: 3-stage cp.async pipeline (wait_group 1)
//   prep:   pack_w + pack_u + coef merged into one launch
// ============================================================================

typedef unsigned long long ull;

#define NB 8192
#define NH 1024

__device__ uint32_t g_Ah[512*20*32*4];   // A frags hi
__device__ uint32_t g_Al[512*20*32*4];
__device__ uint32_t g_Wh[4*128*6*32*4];  // stage2 B frags hi
__device__ uint32_t g_Wl[4*128*6*32*4];
__device__ uint32_t g_Uhi[24576*4];      // stage1 B frags hi
__device__ uint32_t g_Ulo[24576*4];
__device__ float g_cx[4*NH];
__device__ float g_ch[4*NH];
__device__ float g_cb[4*NH];

// ---- helpers ---------------------------------------------------------------
__device__ __forceinline__ float sigm_f(float v) {
    return __fdividef(1.f, 1.f + __expf(-v));
}
__device__ __forceinline__ float tanh_f(float v) {
    return 1.f - __fdividef(2.f, 1.f + __expf(2.f * v));
}
__device__ __forceinline__ void bfsplit(float v, uint16_t& h, uint16_t& l) {
    __nv_bfloat16 bh = __float2bfloat16_rn(v);
    float r = v - __bfloat162float(bh);
    __nv_bfloat16 bl = __float2bfloat16_rn(r);
    h = __bfloat16_as_ushort(bh);
    l = __bfloat16_as_ushort(bl);
}
__device__ __forceinline__ void packpair(float f0, float f1,
                                         uint32_t& hi, uint32_t& lo) {
    uint16_t h0, l0, h1, l1;
    bfsplit(f0, h0, l0); bfsplit(f1, h1, l1);
    hi = (uint32_t)h0 | ((uint32_t)h1 << 16);
    lo = (uint32_t)l0 | ((uint32_t)l1 << 16);
}
__device__ __forceinline__ uint32_t s2u(const void* p) {
    return (uint32_t)__cvta_generic_to_shared(p);
}
__device__ __forceinline__ void cp16(uint32_t dst, const void* src) {
    asm volatile("cp.async.cg.shared.global [%0], [%1], 16;\n"
                 :: "r"(dst), "l"(src));
}
__device__ __forceinline__ void cp_commit() {
    asm volatile("cp.async.commit_group;\n");
}
__device__ __forceinline__ void cp_wait0() {
    asm volatile("cp.async.wait_group 0;\n");
}
__device__ __forceinline__ void cp_wait1() {
    asm volatile("cp.async.wait_group 1;\n");
}
__device__ __forceinline__ void lds128(uint32_t* r, uint32_t a) {
    asm volatile("ld.shared.v4.b32 {%0,%1,%2,%3}, [%4];"
                 : "=r"(r[0]), "=r"(r[1]), "=r"(r[2]), "=r"(r[3]) : "r"(a));
}
__device__ __forceinline__ void sts32(uint32_t a, uint32_t v) {
    asm volatile("st.shared.b32 [%0], %1;" :: "r"(a), "r"(v));
}
__device__ __forceinline__ void mma_bf16(float* d, const uint32_t* a,
                                         const uint32_t* b) {
    asm volatile(
        "mma.sync.aligned.m16n8k16.row.col.f32.bf16.bf16.f32 "
        "{%0,%1,%2,%3}, {%4,%5,%6,%7}, {%8,%9}, {%0,%1,%2,%3};\n"
        : "+f"(d[0]), "+f"(d[1]), "+f"(d[2]), "+f"(d[3])
        : "r"(a[0]), "r"(a[1]), "r"(a[2]), "r"(a[3]), "r"(b[0]), "r"(b[1]));
}

// ============================================================================
// prep_kernel: blocks 0..63 pack_w, 64..159 pack_u, 160..175 coef
// ============================================================================
__global__ void prep_kernel(const float* __restrict__ Vx,
                            const float* __restrict__ Vh0,
                            const float* __restrict__ Vh1,
                            const float* __restrict__ Ux,
                            const float* __restrict__ Uh0,
                            const float* __restrict__ Uh1,
                            const float* __restrict__ bx,
                            const float* __restrict__ bh) {
    __shared__ float V[192][64];
    int tid = threadIdx.x;
    int blk = blockIdx.x;

    if (blk < 64) {
        // ---- pack_w ----
        int jblk = blk & 15, kap = blk >> 4;
        int g = kap >> 1;
        int mh0 = (((kap ^ 1) & 1) << 10) + jblk * 64;
        #pragma unroll
        for (int i = 0; i < 4; i++) {
            int idx = tid + i * 256;
            int jl = idx >> 4, kq = idx & 15;
            float4 v = *(const float4*)
                &Vx[((size_t)(kap * NH + jblk * 64 + jl)) * 64 + kq * 4];
            V[kq * 4 + 0][jl] = v.x;
            V[kq * 4 + 1][jl] = v.y;
            V[kq * 4 + 2][jl] = v.z;
            V[kq * 4 + 3][jl] = v.w;
        }
        #pragma unroll
        for (int i = 0; i < 8; i++) {
            int idx = tid + i * 256;
            int kkr = idx >> 4, jq = idx & 15;
            const float* src = (kkr < 64)
                ? &Vh0[(size_t)g * 131072 + kkr * 2048 + mh0]
                : &Vh1[(size_t)g * 131072 + (kkr - 64) * 2048 + mh0];
            *(float4*)&V[64 + kkr][jq * 4] = *(const float4*)&src[jq * 4];
        }
        __syncthreads();
        #pragma unroll
        for (int i = 0; i < 6; i++) {
            int idx = tid + i * 256;
            int n8l = idx / 192, rem = idx % 192;
            int cc = rem >> 5, lane = rem & 31;
            int jl = n8l * 8 + (lane >> 2), tg = lane & 3;
            uint32_t hi[4], lo[4];
            #pragma unroll
            for (int t = 0; t < 4; t++) {
                int kk = 2 * (cc * 16 + tg + t * 4);
                packpair(V[kk][jl], V[kk + 1][jl], hi[t], lo[t]);
            }
            size_t fo = (((size_t)kap * 128 + jblk * 8 + n8l) * 6 + cc) * 32 + lane;
            *(uint4*)&g_Wh[fo * 4] = make_uint4(hi[0], hi[1], hi[2], hi[3]);
            *(uint4*)&g_Wl[fo * 4] = make_uint4(lo[0], lo[1], lo[2], lo[3]);
        }
    } else if (blk < 160) {
        // ---- pack_u ----
        int idx = (blk - 64) * 256 + tid;
        const float* src;
        int lane, tg, n, cc;
        if (idx < 8192) {
            int n8 = idx >> 10; cc = (idx >> 5) & 31; lane = idx & 31;
            n = n8 * 8 + (lane >> 2);
            src = Ux;
        } else {
            int rem = idx - 8192;
            int e = rem >> 12;
            int n8 = (rem >> 9) & 7; cc = (rem >> 5) & 15; lane = rem & 31;
            n = n8 * 8 + (lane >> 2);
            src = ((e & 1) ? Uh1 : Uh0) + (e >> 1) * 512 * 64;
        }
        tg = lane & 3;
        uint32_t hi[4], lo[4];
        #pragma unroll
        for (int t = 0; t < 4; t++) {
            int kp = cc * 16 + tg + t * 4;
            packpair(src[(size_t)(2 * kp) * 64 + n],
                     src[(size_t)(2 * kp + 1) * 64 + n], hi[t], lo[t]);
        }
        *(uint4*)&g_Uhi[(size_t)idx * 4] = make_uint4(hi[0], hi[1], hi[2], hi[3]);
        *(uint4*)&g_Ulo[(size_t)idx * 4] = make_uint4(lo[0], lo[1], lo[2], lo[3]);
    } else {
        // ---- coef ----
        int idx = (blk - 160) * 256 + tid;
        int j = idx & 1023;
        int kap = idx >> 10;
        int g  = kap >> 1;
        int mh = (((kap ^ 1) & 1) << 10) + j;
        float sx = 0.f, sh = 0.f;
        #pragma unroll 8
        for (int r = 0; r < 64; r++) {
            sx += Ux[j * 64 + r] * Vx[(kap * NH + j) * 64 + r];
            sh += Uh0[j * 64 + r] * Vh0[g * 131072 + r * 2048 + mh];
        }
        g_cx[idx] = sx;
        g_ch[idx] = sh;
        g_cb[idx] = bx[(kap << 10) + j] + bh[((kap ^ 1) << 10) + j];
    }
}

// ============================================================================
// stage1_mma: 5 GEMMs, CTA = 128b x 64n, conflict-free frag smem.
//   A-frag smem: lane' = tg*8+lrow, slot words rotated by 2*(tile&1).
//   buf (24576B): A_hi[0,8K) A_lo[8K,16K) W_hi[16K,20K) W_lo[20K,24K)
// ============================================================================
#define S1_DSMEM (2*24576)

__global__ __launch_bounds__(256, 2)
void stage1_mma(const float* __restrict__ x, const float* __restrict__ h) {
    extern __shared__ char dsm[];
    uint32_t smu = s2u(dsm);

    int tid = threadIdx.x;
    int lane = tid & 31, wid = tid >> 5;
    int tg = lane & 3, lrow = lane >> 2;
    int laneT = tg * 8 + lrow;           // permuted frag lane
    int wb = wid >> 1, wj = wid & 1;
    int b0 = blockIdx.x * 128;
    int cb = blockIdx.y;

    const float* Ap;
    int NC, NCC, ufrag, aoff, outoff;
    if (cb == 0) {
        Ap = x; NC = 32; NCC = 32; ufrag = 0; aoff = 0; outoff = 0;
    } else {
        int e = cb - 1;
        int g = e >> 1, i = e & 1;
        Ap = h; NC = 16; NCC = 16;
        ufrag = 8192 + e * 4096;
        aoff = ((g + i) & 1) * 512;
        outoff = 64 + g * 128 + i * 64;
    }

    float4 pf[4];
    int arow = tid >> 1, acg = tid & 1;

    #define S1_LDG(cc) do {                                                   \
        const float* src = &Ap[(size_t)(b0 + arow) * NH + aoff +              \
                               (cc) * 32 + acg * 16];                         \
        pf[0] = *(const float4*)(src);                                        \
        pf[1] = *(const float4*)(src + 4);                                    \
        pf[2] = *(const float4*)(src + 8);                                    \
        pf[3] = *(const float4*)(src + 12);                                   \
    } while (0)

    // conflict-free frag write: lane'=(q&3)*8+(arow&7), slot rotated by 2*acg
    #define S1_STS(buf) do {                                                  \
        uint32_t bufb = smu + (buf) * 24576;                                  \
        const float* pff = (const float*)pf;                                  \
        uint32_t tb = bufb + (uint32_t)(((arow >> 4) * 2 + acg) * 512);       \
        uint32_t rb = (arow >> 3) & 1;                                        \
        _Pragma("unroll")                                                     \
        for (int q = 0; q < 8; q++) {                                         \
            uint32_t hi, lo;                                                  \
            packpair(pff[2 * q], pff[2 * q + 1], hi, lo);                     \
            uint32_t ltp = (uint32_t)((q & 3) * 8 + (arow & 7));              \
            uint32_t sl  = (uint32_t)(((q >> 2) << 1) + rb);                  \
            uint32_t slp = (sl + 2 * (uint32_t)acg) & 3;                      \
            uint32_t ad = tb + ltp * 16 + slp * 4;                            \
            sts32(ad, hi);                                                    \
            sts32(ad + 8192, lo);                                             \
        }                                                                     \
    } while (0)

    #define S1_CPW(cc, buf) do {                                              \
        int n8 = tid >> 5, ln = tid & 31;                                     \
        uint32_t dst = smu + (buf) * 24576 + 16384 + (n8 * 32 + ln) * 16;     \
        size_t fo = (size_t)(ufrag + (n8 * NCC + (cc)) * 32 + ln) * 4;        \
        cp16(dst, &g_Uhi[fo]);                                                \
        cp16(dst + 4096, &g_Ulo[fo]);                                         \
        cp_commit();                                                          \
    } while (0)

    #define S1_COMPUTE(buf) do {                                              \
        uint32_t bufb = smu + (buf) * 24576;                                  \
        uint32_t bh[4][4], bl[4][4];                                          \
        _Pragma("unroll")                                                     \
        for (int nt = 0; nt < 4; nt++) {                                      \
            uint32_t ba = bufb + 16384 + (((wj * 4 + nt) * 32) + lane) * 16;  \
            lds128(bh[nt], ba);                                               \
            lds128(bl[nt], ba + 4096);                                        \
        }                                                                     \
        _Pragma("unroll")                                                     \
        for (int s = 0; s < 2; s++) {                                         \
            uint32_t ah[2][4], al[2][4];                                      \
            _Pragma("unroll")                                                 \
            for (int mt = 0; mt < 2; mt++) {                                  \
                uint32_t rh[4], rl[4];                                        \
                uint32_t aa = bufb +                                          \
                    ((((wb * 2 + mt) * 2 + s) * 32) + laneT) * 16;            \
                lds128(rh, aa);                                               \
                lds128(rl, aa + 8192);                                        \
                _Pragma("unroll")                                             \
                for (int i = 0; i < 4; i++) {                                 \
                    ah[mt][i] = rh[(i + 2 * s) & 3];                          \
                    al[mt][i] = rl[(i + 2 * s) & 3];                          \
                }                                                             \
            }                                                                 \
            _Pragma("unroll")                                                 \
            for (int nt = 0; nt < 4; nt++) {                                  \
                uint32_t b2h[2] = {bh[nt][s * 2], bh[nt][s * 2 + 1]};         \
                uint32_t b2l[2] = {bl[nt][s * 2], bl[nt][s * 2 + 1]};         \
                _Pragma("unroll")                                             \
                for (int mt = 0; mt < 2; mt++) {                              \
                    mma_bf16(acc[mt][nt], ah[mt], b2h);                       \
                    mma_bf16(acc[mt][nt], al[mt], b2h);                       \
                    mma_bf16(acc[mt][nt], ah[mt], b2l);                       \
                }                                                             \
            }                                                                 \
        }                                                                     \
    } while (0)

    float acc[2][4][4];
    #pragma unroll
    for (int a1 = 0; a1 < 2; a1++)
        #pragma unroll
        for (int a2 = 0; a2 < 4; a2++)
            #pragma unroll
            for (int a3 = 0; a3 < 4; a3++) acc[a1][a2][a3] = 0.f;

    S1_LDG(0);
    S1_CPW(0, 0);
    S1_STS(0);
    cp_wait0();
    __syncthreads();

    for (int cc = 0; cc < NC; cc++) {
        int buf = cc & 1;
        if (cc < NC - 1) {
            S1_CPW(cc + 1, buf ^ 1);
            S1_LDG(cc + 1);
        }
        S1_COMPUTE(buf);
        if (cc < NC - 1) {
            S1_STS(buf ^ 1);
            cp_wait0();
        }
        __syncthreads();
    }

    // epilogue: C-frags -> g_Ah/g_Al (standard frag layout; unchanged)
    #pragma unroll
    for (int mt = 0; mt < 2; mt++) {
        int b16g = (b0 + wb * 32 + mt * 16) >> 4;
        #pragma unroll
        for (int ntp = 0; ntp < 2; ntp++) {
            int k16g = (outoff >> 4) + wj * 2 + ntp;
            uint32_t hi[4], lo[4];
            packpair(acc[mt][2 * ntp][0],     acc[mt][2 * ntp][1],     hi[0], lo[0]);
            packpair(acc[mt][2 * ntp][2],     acc[mt][2 * ntp][3],     hi[1], lo[1]);
            packpair(acc[mt][2 * ntp + 1][0], acc[mt][2 * ntp + 1][1], hi[2], lo[2]);
            packpair(acc[mt][2 * ntp + 1][2], acc[mt][2 * ntp + 1][3], hi[3], lo[3]);
            size_t fo = ((size_t)b16g * 20 + k16g) * 32 + lane;
            *(uint4*)&g_Ah[fo * 4] = make_uint4(hi[0], hi[1], hi[2], hi[3]);
            *(uint4*)&g_Al[fo * 4] = make_uint4(lo[0], lo[1], lo[2], lo[3]);
        }
    }
}

// ============================================================================
// stage2_mma: 3-stage cp.async pipeline + fused LSTM epilogue (2 CTAs/SM).
//   3 bufs x 24576 + 32768 spill = 106496 B dynamic.
// ============================================================================
#define S2_DSMEM (3*24576 + 32768)

__global__ __launch_bounds__(256, 2)
void stage2_mma(const float* __restrict__ x, const float* __restrict__ h,
                const float* __restrict__ c, const float* __restrict__ dia_x,
                const float* __restrict__ dia_h, float* __restrict__ out) {
    extern __shared__ char dsm[];
    __shared__ float epi[896];
    uint32_t smu = s2u(dsm);
    float* spill = (float*)(dsm + 3 * 24576);

    int tid = threadIdx.x;
    int lane = tid & 31, wid = tid >> 5;
    int tg = lane & 3, lrow = lane >> 2;
    int wb = wid >> 2, wj = wid & 3;
    int j0 = blockIdx.x * 64;
    int b0 = blockIdx.y * 64;
    int b16base = b0 >> 4;
    int n8base = j0 >> 3;

    for (int i = tid; i < 896; i += 256) {
        float v;
        if (i < 256)       v = g_cx[(i >> 6) * 1024 + j0 + (i & 63)];
        else if (i < 512)  { int q = i - 256; v = g_ch[(q >> 6) * 1024 + j0 + (q & 63)]; }
        else if (i < 768)  { int q = i - 512; v = g_cb[(q >> 6) * 1024 + j0 + (q & 63)]; }
        else if (i < 832)  v = dia_x[j0 + i - 768];
        else               v = dia_h[j0 + i - 832];
        epi[i] = v;
    }

    #define FILL(buf, p, cc) do {                                             \
        uint32_t bufb = smu + (buf) * 24576;                                  \
        int k16base = ((cc) < 2) ? (cc) * 2 : (p) * 8 + (cc) * 2;             \
        {                                                                     \
            int b16l = tid >> 6, k16l = (tid >> 5) & 1, ln = tid & 31;        \
            size_t fo = (size_t)(((b16base + b16l) * 20 + k16base + k16l)     \
                                 * 32 + ln) * 4;                              \
            uint32_t dst = bufb + ((b16l * 2 + k16l) * 32 + ln) * 16;         \
            cp16(dst, &g_Ah[fo]);                                             \
            cp16(dst + 4096, &g_Al[fo]);                                      \
        }                                                                     \
        _Pragma("unroll")                                                     \
        for (int i2 = 0; i2 < 2; i2++) {                                      \
            int idx = tid + i2 * 256;                                         \
            int gl = idx >> 8, n8 = (idx >> 5) & 7, ln = idx & 31;            \
            size_t fo = (size_t)((((2 * (p) + gl) * 128 + n8base + n8) * 6    \
                                  + (cc)) * 32 + ln) * 4;                     \
            uint32_t dst = bufb + 8192 + ((gl * 8 + n8) * 32 + ln) * 16;      \
            cp16(dst, &g_Wh[fo]);                                             \
            cp16(dst + 8192, &g_Wl[fo]);                                      \
        }                                                                     \
        cp_commit();                                                          \
    } while (0)

    #define COMPUTE(ACC, buf) do {                                            \
        uint32_t bufb = smu + (buf) * 24576;                                  \
        uint32_t bh[2][2][4], bl[2][2][4];                                    \
        _Pragma("unroll")                                                     \
        for (int gl = 0; gl < 2; gl++)                                        \
            _Pragma("unroll")                                                 \
            for (int nt = 0; nt < 2; nt++) {                                  \
                uint32_t ba = bufb + 8192 +                                   \
                    ((gl * 8 + wj * 2 + nt) * 32 + lane) * 16;                \
                lds128(bh[gl][nt], ba);                                       \
                lds128(bl[gl][nt], ba + 8192);                                \
            }                                                                 \
        _Pragma("unroll")                                                     \
        for (int s = 0; s < 2; s++) {                                         \
            uint32_t ah[2][4], al[2][4];                                      \
            _Pragma("unroll")                                                 \
            for (int mt = 0; mt < 2; mt++) {                                  \
                uint32_t aa = bufb +                                          \
                    (((wb * 2 + mt) * 2 + s) * 32 + lane) * 16;               \
                lds128(ah[mt], aa);                                           \
                lds128(al[mt], aa + 4096);                                    \
            }                                                                 \
            _Pragma("unroll")                                                 \
            for (int gl = 0; gl < 2; gl++)                                    \
                _Pragma("unroll")                                             \
                for (int nt = 0; nt < 2; nt++) {                              \
                    uint32_t b2h[2] = {bh[gl][nt][s * 2], bh[gl][nt][s * 2 + 1]}; \
                    uint32_t b2l[2] = {bl[gl][nt][s * 2], bl[gl][nt][s * 2 + 1]}; \
                    _Pragma("unroll")                                         \
                    for (int mt = 0; mt < 2; mt++) {                          \
                        mma_bf16(ACC[mt][nt][gl], ah[mt], b2h);               \
                        mma_bf16(ACC[mt][nt][gl], al[mt], b2h);               \
                        mma_bf16(ACC[mt][nt][gl], ah[mt], b2l);               \
                    }                                                         \
                }                                                             \
        }                                                                     \
    } while (0)

    // prologue: fill chunks 0,1
    FILL(0, 0, 0);
    FILL(1, 0, 1);

    // ---------------- phase 0 (gates i,f), chunks 0..5 ----------------
    {
        float acc0[2][2][2][4];
        #pragma unroll
        for (int a1 = 0; a1 < 2; a1++)
            #pragma unroll
            for (int a2 = 0; a2 < 2; a2++)
                #pragma unroll
                for (int a3 = 0; a3 < 2; a3++)
                    #pragma unroll
                    for (int a4 = 0; a4 < 4; a4++) acc0[a1][a2][a3][a4] = 0.f;

        for (int ci = 0; ci < 6; ci++) {
            cp_wait1();
            __syncthreads();
            int nc = ci + 2;
            FILL(nc % 3, nc / 6, nc % 6);
            COMPUTE(acc0, ci % 3);
        }
        #pragma unroll
        for (int mt = 0; mt < 2; mt++)
            #pragma unroll
            for (int nt = 0; nt < 2; nt++)
                #pragma unroll
                for (int gl = 0; gl < 2; gl++)
                    #pragma unroll
                    for (int dr = 0; dr < 4; dr++) {
                        int e = ((mt * 2 + nt) * 2 + gl) * 4 + dr;
                        spill[e * 256 + tid] = acc0[mt][nt][gl][dr];
                    }
    }

    // ---------------- phase 1 (gates o,n), chunks 6..11 ----------------
    float acc1[2][2][2][4];
    #pragma unroll
    for (int a1 = 0; a1 < 2; a1++)
        #pragma unroll
        for (int a2 = 0; a2 < 2; a2++)
            #pragma unroll
            for (int a3 = 0; a3 < 2; a3++)
                #pragma unroll
                for (int a4 = 0; a4 < 4; a4++) acc1[a1][a2][a3][a4] = 0.f;

    for (int ci = 6; ci < 12; ci++) {
        if (ci < 11) cp_wait1(); else cp_wait0();
        __syncthreads();
        int nc = ci + 2;
        if (nc < 12) FILL(nc % 3, 1, nc % 6);
        COMPUTE(acc1, ci % 3);
    }

    // ---- fused LSTM epilogue ------------------------------------------------
    #pragma unroll
    for (int mt = 0; mt < 2; mt++) {
        #pragma unroll
        for (int rr = 0; rr < 2; rr++) {
            int b = b0 + wb * 32 + mt * 16 + rr * 8 + lrow;
            #pragma unroll
            for (int nt = 0; nt < 2; nt++) {
                int jj = wj * 16 + nt * 8 + 2 * tg;
                size_t off = (size_t)b * NH + j0 + jj;
                float2 xv = *(const float2*)&x[off];
                float2 hv = *(const float2*)&h[off];
                float2 cv = *(const float2*)&c[off];
                float xa[2] = {xv.x, xv.y};
                float ha[2] = {hv.x, hv.y};
                float ca[2] = {cv.x, cv.y};
                float hn[2], cn[2];
                #pragma unroll
                for (int e = 0; e < 2; e++) {
                    int jc = jj + e;
                    int dr = rr * 2 + e;
                    int eb = ((mt * 2 + nt) * 2) * 4 + dr;
                    float gi = spill[eb * 256 + tid];
                    float gf = spill[(eb + 4) * 256 + tid];
                    float go = acc1[mt][nt][0][dr];
                    float gn = acc1[mt][nt][1][dr];
                    float base = epi[768 + jc] * xa[e] + epi[832 + jc] * ha[e];
                    float v0 = gi - xa[e] * epi[jc]       - ha[e] * epi[256 + jc] + epi[512 + jc] + base;
                    float v1 = gf - xa[e] * epi[64 + jc]  - ha[e] * epi[320 + jc] + epi[576 + jc] + base;
                    float v2 = go - xa[e] * epi[128 + jc] - ha[e] * epi[384 + jc] + epi[640 + jc] + base;
                    float v3 = gn - xa[e] * epi[192 + jc] - ha[e] * epi[448 + jc] + epi[704 + jc] + base;
                    float ig = sigm_f(v0);
                    float fg = sigm_f(v1);
                    float og = sigm_f(v2);
                    float ng = tanh_f(v3);
                    float cnx = fg * ca[e] + ig * ng;
                    cn[e] = cnx;
                    hn[e] = og * tanh_f(cnx);
                }
                *(float2*)&out[off] = make_float2(hn[0], hn[1]);
                *(float2*)&out[(size_t)NB * NH + off] = make_float2(cn[0], cn[1]);
            }
        }
    }
}

// ============================================================================
extern "C" void kernel_launch(void* const* d_in, const int* in_sizes, int n_in,
                              void* d_out, int out_size) {
    const float* x     = (const float*)d_in[0];
    const float* h     = (const float*)d_in[1];
    const float* c     = (const float*)d_in[2];
    const float* dia_x = (const float*)d_in[3];
    const float* dia_h = (const float*)d_in[4];
    const float* Ux    = (const float*)d_in[5];
    const float* Vx    = (const float*)d_in[6];
    const float* Uh0   = (const float*)d_in[7];
    const float* Vh0   = (const float*)d_in[8];
    const float* Uh1   = (const float*)d_in[9];
    const float* Vh1   = (const float*)d_in[10];
    const float* bx    = (const float*)d_in[11];
    const float* bh    = (const float*)d_in[12];
    float* out = (float*)d_out;

    cudaFuncSetAttribute(stage1_mma,
                         cudaFuncAttributeMaxDynamicSharedMemorySize, S1_DSMEM);
    cudaFuncSetAttribute(stage2_mma,
                         cudaFuncAttributeMaxDynamicSharedMemorySize, S2_DSMEM);

    prep_kernel<<<176, 256>>>(Vx, Vh0, Vh1, Ux, Uh0, Uh1, bx, bh);
    stage1_mma<<<dim3(64, 5), 256, S1_DSMEM>>>(x, h);
    stage2_mma<<<dim3(16, 128), 256, S2_DSMEM>>>(x, h, c, dia_x, dia_h, out);
}

// round 12
// speedup vs baseline: 2.9235x; 1.1564x over previous
#include <cuda_runtime.h>
#include <cuda_bf16.h>
#include <cstdint>

// ============================================================================
// myVMLSTMCell fused low-rank LSTM — R12:
//   pack_u standalone (tiny); pack_w + coef absorbed into stage1's grid
//   (blockIdx.y == 5) so they overlap the stage1 GEMM wave tail.
//   stage1: conflict-free frag STS; stage2: 3-stage cp.async pipeline.
// ============================================================================

typedef unsigned long long ull;

#define NB 8192
#define NH 1024

__device__ uint32_t g_Ah[512*20*32*4];   // A frags hi
__device__ uint32_t g_Al[512*20*32*4];
__device__ uint32_t g_Wh[4*128*6*32*4];  // stage2 B frags hi
__device__ uint32_t g_Wl[4*128*6*32*4];
__device__ uint32_t g_Uhi[24576*4];      // stage1 B frags hi
__device__ uint32_t g_Ulo[24576*4];
__device__ float g_cx[4*NH];
__device__ float g_ch[4*NH];
__device__ float g_cb[4*NH];

// ---- helpers ---------------------------------------------------------------
__device__ __forceinline__ float sigm_f(float v) {
    return __fdividef(1.f, 1.f + __expf(-v));
}
__device__ __forceinline__ float tanh_f(float v) {
    return 1.f - __fdividef(2.f, 1.f + __expf(2.f * v));
}
__device__ __forceinline__ void bfsplit(float v, uint16_t& h, uint16_t& l) {
    __nv_bfloat16 bh = __float2bfloat16_rn(v);
    float r = v - __bfloat162float(bh);
    __nv_bfloat16 bl = __float2bfloat16_rn(r);
    h = __bfloat16_as_ushort(bh);
    l = __bfloat16_as_ushort(bl);
}
__device__ __forceinline__ void packpair(float f0, float f1,
                                         uint32_t& hi, uint32_t& lo) {
    uint16_t h0, l0, h1, l1;
    bfsplit(f0, h0, l0); bfsplit(f1, h1, l1);
    hi = (uint32_t)h0 | ((uint32_t)h1 << 16);
    lo = (uint32_t)l0 | ((uint32_t)l1 << 16);
}
__device__ __forceinline__ uint32_t s2u(const void* p) {
    return (uint32_t)__cvta_generic_to_shared(p);
}
__device__ __forceinline__ void cp16(uint32_t dst, const void* src) {
    asm volatile("cp.async.cg.shared.global [%0], [%1], 16;\n"
                 :: "r"(dst), "l"(src));
}
__device__ __forceinline__ void cp_commit() {
    asm volatile("cp.async.commit_group;\n");
}
__device__ __forceinline__ void cp_wait0() {
    asm volatile("cp.async.wait_group 0;\n");
}
__device__ __forceinline__ void cp_wait1() {
    asm volatile("cp.async.wait_group 1;\n");
}
__device__ __forceinline__ void lds128(uint32_t* r, uint32_t a) {
    asm volatile("ld.shared.v4.b32 {%0,%1,%2,%3}, [%4];"
                 : "=r"(r[0]), "=r"(r[1]), "=r"(r[2]), "=r"(r[3]) : "r"(a));
}
__device__ __forceinline__ void sts32(uint32_t a, uint32_t v) {
    asm volatile("st.shared.b32 [%0], %1;" :: "r"(a), "r"(v));
}
__device__ __forceinline__ void mma_bf16(float* d, const uint32_t* a,
                                         const uint32_t* b) {
    asm volatile(
        "mma.sync.aligned.m16n8k16.row.col.f32.bf16.bf16.f32 "
        "{%0,%1,%2,%3}, {%4,%5,%6,%7}, {%8,%9}, {%0,%1,%2,%3};\n"
        : "+f"(d[0]), "+f"(d[1]), "+f"(d[2]), "+f"(d[3])
        : "r"(a[0]), "r"(a[1]), "r"(a[2]), "r"(a[3]), "r"(b[0]), "r"(b[1]));
}

// ============================================================================
// pack_u: stage1 B frags (must precede stage1). 96 blocks x 256.
// ============================================================================
__global__ void pack_u_kernel(const float* __restrict__ Ux,
                              const float* __restrict__ Uh0,
                              const float* __restrict__ Uh1) {
    int idx = blockIdx.x * 256 + threadIdx.x;
    if (idx >= 24576) return;
    const float* src;
    int lane, tg, n, cc;
    if (idx < 8192) {
        int n8 = idx >> 10; cc = (idx >> 5) & 31; lane = idx & 31;
        n = n8 * 8 + (lane >> 2);
        src = Ux;
    } else {
        int rem = idx - 8192;
        int e = rem >> 12;
        int n8 = (rem >> 9) & 7; cc = (rem >> 5) & 15; lane = rem & 31;
        n = n8 * 8 + (lane >> 2);
        src = ((e & 1) ? Uh1 : Uh0) + (e >> 1) * 512 * 64;
    }
    tg = lane & 3;
    uint32_t hi[4], lo[4];
    #pragma unroll
    for (int t = 0; t < 4; t++) {
        int kp = cc * 16 + tg + t * 4;
        packpair(src[(size_t)(2 * kp) * 64 + n],
                 src[(size_t)(2 * kp + 1) * 64 + n], hi[t], lo[t]);
    }
    *(uint4*)&g_Uhi[(size_t)idx * 4] = make_uint4(hi[0], hi[1], hi[2], hi[3]);
    *(uint4*)&g_Ulo[(size_t)idx * 4] = make_uint4(lo[0], lo[1], lo[2], lo[3]);
}

// ============================================================================
// stage1_mma: grid (64, 6).
//   y<5 : GEMM 128b x 64n (conflict-free frag smem)
//   y==5: pack_w (blockIdx.x -> (jblk,kap)) + coef (warp-per-entry reduce)
// ============================================================================
#define S1_DSMEM (2*24576)

__global__ __launch_bounds__(256, 2)
void stage1_mma(const float* __restrict__ x, const float* __restrict__ h,
                const float* __restrict__ Vx, const float* __restrict__ Vh0,
                const float* __restrict__ Vh1, const float* __restrict__ Ux,
                const float* __restrict__ Uh0, const float* __restrict__ bx,
                const float* __restrict__ bh) {
    extern __shared__ char dsm[];
    uint32_t smu = s2u(dsm);

    int tid = threadIdx.x;
    int lane = tid & 31, wid = tid >> 5;
    int tg = lane & 3, lrow = lane >> 2;

    if (blockIdx.y == 5) {
        // ================== pack_w + coef ==================
        float (*V)[64] = (float(*)[64])dsm;   // 192x64 = 48KB
        int blk = blockIdx.x;
        int jblk = blk & 15, kap = blk >> 4;
        int g = kap >> 1;
        int mh0 = (((kap ^ 1) & 1) << 10) + jblk * 64;

        #pragma unroll
        for (int i = 0; i < 4; i++) {
            int idx = tid + i * 256;
            int jl = idx >> 4, kq = idx & 15;
            float4 v = *(const float4*)
                &Vx[((size_t)(kap * NH + jblk * 64 + jl)) * 64 + kq * 4];
            V[kq * 4 + 0][jl] = v.x;
            V[kq * 4 + 1][jl] = v.y;
            V[kq * 4 + 2][jl] = v.z;
            V[kq * 4 + 3][jl] = v.w;
        }
        #pragma unroll
        for (int i = 0; i < 8; i++) {
            int idx = tid + i * 256;
            int kkr = idx >> 4, jq = idx & 15;
            const float* src = (kkr < 64)
                ? &Vh0[(size_t)g * 131072 + kkr * 2048 + mh0]
                : &Vh1[(size_t)g * 131072 + (kkr - 64) * 2048 + mh0];
            *(float4*)&V[64 + kkr][jq * 4] = *(const float4*)&src[jq * 4];
        }
        __syncthreads();
        #pragma unroll
        for (int i = 0; i < 6; i++) {
            int idx = tid + i * 256;
            int n8l = idx / 192, rem = idx % 192;
            int cc = rem >> 5, ln = rem & 31;
            int jl = n8l * 8 + (ln >> 2), tgw = ln & 3;
            uint32_t hi[4], lo[4];
            #pragma unroll
            for (int t = 0; t < 4; t++) {
                int kk = 2 * (cc * 16 + tgw + t * 4);
                packpair(V[kk][jl], V[kk + 1][jl], hi[t], lo[t]);
            }
            size_t fo = (((size_t)kap * 128 + jblk * 8 + n8l) * 6 + cc) * 32 + ln;
            *(uint4*)&g_Wh[fo * 4] = make_uint4(hi[0], hi[1], hi[2], hi[3]);
            *(uint4*)&g_Wl[fo * 4] = make_uint4(lo[0], lo[1], lo[2], lo[3]);
        }
        // ---- coef: 64 entries per block, warp-per-entry (8 per warp) ----
        int base = blk * 64;
        #pragma unroll 1
        for (int t8 = 0; t8 < 8; t8++) {
            int idx = base + wid * 8 + t8;
            int j = idx & 1023;
            int kapc = idx >> 10;
            int gc = kapc >> 1;
            int mh = (((kapc ^ 1) & 1) << 10) + j;
            float sx = 0.f, sh = 0.f;
            #pragma unroll
            for (int rr = 0; rr < 2; rr++) {
                int r = lane + rr * 32;
                sx += Ux[j * 64 + r] * Vx[(size_t)(kapc * NH + j) * 64 + r];
                sh += Uh0[j * 64 + r]
                    * Vh0[(size_t)gc * 131072 + (size_t)r * 2048 + mh];
            }
            #pragma unroll
            for (int o = 16; o; o >>= 1) {
                sx += __shfl_xor_sync(0xFFFFFFFFu, sx, o);
                sh += __shfl_xor_sync(0xFFFFFFFFu, sh, o);
            }
            if (lane == 0) {
                g_cx[idx] = sx;
                g_ch[idx] = sh;
                g_cb[idx] = bx[(kapc << 10) + j] + bh[((kapc ^ 1) << 10) + j];
            }
        }
        return;
    }

    // ================== GEMM path ==================
    int laneT = tg * 8 + lrow;
    int wb = wid >> 1, wj = wid & 1;
    int b0 = blockIdx.x * 128;
    int cb = blockIdx.y;

    const float* Ap;
    int NC, NCC, ufrag, aoff, outoff;
    if (cb == 0) {
        Ap = x; NC = 32; NCC = 32; ufrag = 0; aoff = 0; outoff = 0;
    } else {
        int e = cb - 1;
        int g = e >> 1, i = e & 1;
        Ap = h; NC = 16; NCC = 16;
        ufrag = 8192 + e * 4096;
        aoff = ((g + i) & 1) * 512;
        outoff = 64 + g * 128 + i * 64;
    }

    float4 pf[4];
    int arow = tid >> 1, acg = tid & 1;

    #define S1_LDG(cc) do {                                                   \
        const float* src = &Ap[(size_t)(b0 + arow) * NH + aoff +              \
                               (cc) * 32 + acg * 16];                         \
        pf[0] = *(const float4*)(src);                                        \
        pf[1] = *(const float4*)(src + 4);                                    \
        pf[2] = *(const float4*)(src + 8);                                    \
        pf[3] = *(const float4*)(src + 12);                                   \
    } while (0)

    #define S1_STS(buf) do {                                                  \
        uint32_t bufb = smu + (buf) * 24576;                                  \
        const float* pff = (const float*)pf;                                  \
        uint32_t tb = bufb + (uint32_t)(((arow >> 4) * 2 + acg) * 512);       \
        uint32_t rb = (arow >> 3) & 1;                                        \
        _Pragma("unroll")                                                     \
        for (int q = 0; q < 8; q++) {                                         \
            uint32_t hi, lo;                                                  \
            packpair(pff[2 * q], pff[2 * q + 1], hi, lo);                     \
            uint32_t ltp = (uint32_t)((q & 3) * 8 + (arow & 7));              \
            uint32_t sl  = (uint32_t)(((q >> 2) << 1) + rb);                  \
            uint32_t slp = (sl + 2 * (uint32_t)acg) & 3;                      \
            uint32_t ad = tb + ltp * 16 + slp * 4;                            \
            sts32(ad, hi);                                                    \
            sts32(ad + 8192, lo);                                             \
        }                                                                     \
    } while (0)

    #define S1_CPW(cc, buf) do {                                              \
        int n8 = tid >> 5, ln = tid & 31;                                     \
        uint32_t dst = smu + (buf) * 24576 + 16384 + (n8 * 32 + ln) * 16;     \
        size_t fo = (size_t)(ufrag + (n8 * NCC + (cc)) * 32 + ln) * 4;        \
        cp16(dst, &g_Uhi[fo]);                                                \
        cp16(dst + 4096, &g_Ulo[fo]);                                         \
        cp_commit();                                                          \
    } while (0)

    #define S1_COMPUTE(buf) do {                                              \
        uint32_t bufb = smu + (buf) * 24576;                                  \
        uint32_t bh[4][4], bl[4][4];                                          \
        _Pragma("unroll")                                                     \
        for (int nt = 0; nt < 4; nt++) {                                      \
            uint32_t ba = bufb + 16384 + (((wj * 4 + nt) * 32) + lane) * 16;  \
            lds128(bh[nt], ba);                                               \
            lds128(bl[nt], ba + 4096);                                        \
        }                                                                     \
        _Pragma("unroll")                                                     \
        for (int s = 0; s < 2; s++) {                                         \
            uint32_t ah[2][4], al[2][4];                                      \
            _Pragma("unroll")                                                 \
            for (int mt = 0; mt < 2; mt++) {                                  \
                uint32_t rh[4], rl[4];                                        \
                uint32_t aa = bufb +                                          \
                    ((((wb * 2 + mt) * 2 + s) * 32) + laneT) * 16;            \
                lds128(rh, aa);                                               \
                lds128(rl, aa + 8192);                                        \
                _Pragma("unroll")                                             \
                for (int i = 0; i < 4; i++) {                                 \
                    ah[mt][i] = rh[(i + 2 * s) & 3];                          \
                    al[mt][i] = rl[(i + 2 * s) & 3];                          \
                }                                                             \
            }                                                                 \
            _Pragma("unroll")                                                 \
            for (int nt = 0; nt < 4; nt++) {                                  \
                uint32_t b2h[2] = {bh[nt][s * 2], bh[nt][s * 2 + 1]};         \
                uint32_t b2l[2] = {bl[nt][s * 2], bl[nt][s * 2 + 1]};         \
                _Pragma("unroll")                                             \
                for (int mt = 0; mt < 2; mt++) {                              \
                    mma_bf16(acc[mt][nt], ah[mt], b2h);                       \
                    mma_bf16(acc[mt][nt], al[mt], b2h);                       \
                    mma_bf16(acc[mt][nt], ah[mt], b2l);                       \
                }                                                             \
            }                                                                 \
        }                                                                     \
    } while (0)

    float acc[2][4][4];
    #pragma unroll
    for (int a1 = 0; a1 < 2; a1++)
        #pragma unroll
        for (int a2 = 0; a2 < 4; a2++)
            #pragma unroll
            for (int a3 = 0; a3 < 4; a3++) acc[a1][a2][a3] = 0.f;

    S1_LDG(0);
    S1_CPW(0, 0);
    S1_STS(0);
    cp_wait0();
    __syncthreads();

    for (int cc = 0; cc < NC; cc++) {
        int buf = cc & 1;
        if (cc < NC - 1) {
            S1_CPW(cc + 1, buf ^ 1);
            S1_LDG(cc + 1);
        }
        S1_COMPUTE(buf);
        if (cc < NC - 1) {
            S1_STS(buf ^ 1);
            cp_wait0();
        }
        __syncthreads();
    }

    #pragma unroll
    for (int mt = 0; mt < 2; mt++) {
        int b16g = (b0 + wb * 32 + mt * 16) >> 4;
        #pragma unroll
        for (int ntp = 0; ntp < 2; ntp++) {
            int k16g = (outoff >> 4) + wj * 2 + ntp;
            uint32_t hi[4], lo[4];
            packpair(acc[mt][2 * ntp][0],     acc[mt][2 * ntp][1],     hi[0], lo[0]);
            packpair(acc[mt][2 * ntp][2],     acc[mt][2 * ntp][3],     hi[1], lo[1]);
            packpair(acc[mt][2 * ntp + 1][0], acc[mt][2 * ntp + 1][1], hi[2], lo[2]);
            packpair(acc[mt][2 * ntp + 1][2], acc[mt][2 * ntp + 1][3], hi[3], lo[3]);
            size_t fo = ((size_t)b16g * 20 + k16g) * 32 + lane;
            *(uint4*)&g_Ah[fo * 4] = make_uint4(hi[0], hi[1], hi[2], hi[3]);
            *(uint4*)&g_Al[fo * 4] = make_uint4(lo[0], lo[1], lo[2], lo[3]);
        }
    }
}

// ============================================================================
// stage2_mma: 3-stage cp.async pipeline + fused LSTM epilogue (2 CTAs/SM).
// ============================================================================
#define S2_DSMEM (3*24576 + 32768)

__global__ __launch_bounds__(256, 2)
void stage2_mma(const float* __restrict__ x, const float* __restrict__ h,
                const float* __restrict__ c, const float* __restrict__ dia_x,
                const float* __restrict__ dia_h, float* __restrict__ out) {
    extern __shared__ char dsm[];
    __shared__ float epi[896];
    uint32_t smu = s2u(dsm);
    float* spill = (float*)(dsm + 3 * 24576);

    int tid = threadIdx.x;
    int lane = tid & 31, wid = tid >> 5;
    int tg = lane & 3, lrow = lane >> 2;
    int wb = wid >> 2, wj = wid & 3;
    int j0 = blockIdx.x * 64;
    int b0 = blockIdx.y * 64;
    int b16base = b0 >> 4;
    int n8base = j0 >> 3;

    for (int i = tid; i < 896; i += 256) {
        float v;
        if (i < 256)       v = g_cx[(i >> 6) * 1024 + j0 + (i & 63)];
        else if (i < 512)  { int q = i - 256; v = g_ch[(q >> 6) * 1024 + j0 + (q & 63)]; }
        else if (i < 768)  { int q = i - 512; v = g_cb[(q >> 6) * 1024 + j0 + (q & 63)]; }
        else if (i < 832)  v = dia_x[j0 + i - 768];
        else               v = dia_h[j0 + i - 832];
        epi[i] = v;
    }

    #define FILL(buf, p, cc) do {                                             \
        uint32_t bufb = smu + (buf) * 24576;                                  \
        int k16base = ((cc) < 2) ? (cc) * 2 : (p) * 8 + (cc) * 2;             \
        {                                                                     \
            int b16l = tid >> 6, k16l = (tid >> 5) & 1, ln = tid & 31;        \
            size_t fo = (size_t)(((b16base + b16l) * 20 + k16base + k16l)     \
                                 * 32 + ln) * 4;                              \
            uint32_t dst = bufb + ((b16l * 2 + k16l) * 32 + ln) * 16;         \
            cp16(dst, &g_Ah[fo]);                                             \
            cp16(dst + 4096, &g_Al[fo]);                                      \
        }                                                                     \
        _Pragma("unroll")                                                     \
        for (int i2 = 0; i2 < 2; i2++) {                                      \
            int idx = tid + i2 * 256;                                         \
            int gl = idx >> 8, n8 = (idx >> 5) & 7, ln = idx & 31;            \
            size_t fo = (size_t)((((2 * (p) + gl) * 128 + n8base + n8) * 6    \
                                  + (cc)) * 32 + ln) * 4;                     \
            uint32_t dst = bufb + 8192 + ((gl * 8 + n8) * 32 + ln) * 16;      \
            cp16(dst, &g_Wh[fo]);                                             \
            cp16(dst + 8192, &g_Wl[fo]);                                      \
        }                                                                     \
        cp_commit();                                                          \
    } while (0)

    #define COMPUTE(ACC, buf) do {                                            \
        uint32_t bufb = smu + (buf) * 24576;                                  \
        uint32_t bh[2][2][4], bl[2][2][4];                                    \
        _Pragma("unroll")                                                     \
        for (int gl = 0; gl < 2; gl++)                                        \
            _Pragma("unroll")                                                 \
            for (int nt = 0; nt < 2; nt++) {                                  \
                uint32_t ba = bufb + 8192 +                                   \
                    ((gl * 8 + wj * 2 + nt) * 32 + lane) * 16;                \
                lds128(bh[gl][nt], ba);                                       \
                lds128(bl[gl][nt], ba + 8192);                                \
            }                                                                 \
        _Pragma("unroll")                                                     \
        for (int s = 0; s < 2; s++) {                                         \
            uint32_t ah[2][4], al[2][4];                                      \
            _Pragma("unroll")                                                 \
            for (int mt = 0; mt < 2; mt++) {                                  \
                uint32_t aa = bufb +                                          \
                    (((wb * 2 + mt) * 2 + s) * 32 + lane) * 16;               \
                lds128(ah[mt], aa);                                           \
                lds128(al[mt], aa + 4096);                                    \
            }                                                                 \
            _Pragma("unroll")                                                 \
            for (int gl = 0; gl < 2; gl++)                                    \
                _Pragma("unroll")                                             \
                for (int nt = 0; nt < 2; nt++) {                              \
                    uint32_t b2h[2] = {bh[gl][nt][s * 2], bh[gl][nt][s * 2 + 1]}; \
                    uint32_t b2l[2] = {bl[gl][nt][s * 2], bl[gl][nt][s * 2 + 1]}; \
                    _Pragma("unroll")                                         \
                    for (int mt = 0; mt < 2; mt++) {                          \
                        mma_bf16(ACC[mt][nt][gl], ah[mt], b2h);               \
                        mma_bf16(ACC[mt][nt][gl], al[mt], b2h);               \
                        mma_bf16(ACC[mt][nt][gl], ah[mt], b2l);               \
                    }                                                         \
                }                                                             \
        }                                                                     \
    } while (0)

    FILL(0, 0, 0);
    FILL(1, 0, 1);

    // ---------------- phase 0 (gates i,f) ----------------
    {
        float acc0[2][2][2][4];
        #pragma unroll
        for (int a1 = 0; a1 < 2; a1++)
            #pragma unroll
            for (int a2 = 0; a2 < 2; a2++)
                #pragma unroll
                for (int a3 = 0; a3 < 2; a3++)
                    #pragma unroll
                    for (int a4 = 0; a4 < 4; a4++) acc0[a1][a2][a3][a4] = 0.f;

        for (int ci = 0; ci < 6; ci++) {
            cp_wait1();
            __syncthreads();
            int nc = ci + 2;
            FILL(nc % 3, nc / 6, nc % 6);
            COMPUTE(acc0, ci % 3);
        }
        #pragma unroll
        for (int mt = 0; mt < 2; mt++)
            #pragma unroll
            for (int nt = 0; nt < 2; nt++)
                #pragma unroll
                for (int gl = 0; gl < 2; gl++)
                    #pragma unroll
                    for (int dr = 0; dr < 4; dr++) {
                        int e = ((mt * 2 + nt) * 2 + gl) * 4 + dr;
                        spill[e * 256 + tid] = acc0[mt][nt][gl][dr];
                    }
    }

    // ---------------- phase 1 (gates o,n) ----------------
    float acc1[2][2][2][4];
    #pragma unroll
    for (int a1 = 0; a1 < 2; a1++)
        #pragma unroll
        for (int a2 = 0; a2 < 2; a2++)
            #pragma unroll
            for (int a3 = 0; a3 < 2; a3++)
                #pragma unroll
                for (int a4 = 0; a4 < 4; a4++) acc1[a1][a2][a3][a4] = 0.f;

    for (int ci = 6; ci < 12; ci++) {
        if (ci < 11) cp_wait1(); else cp_wait0();
        __syncthreads();
        int nc = ci + 2;
        if (nc < 12) FILL(nc % 3, 1, nc % 6);
        COMPUTE(acc1, ci % 3);
    }

    // ---- fused LSTM epilogue ------------------------------------------------
    #pragma unroll
    for (int mt = 0; mt < 2; mt++) {
        #pragma unroll
        for (int rr = 0; rr < 2; rr++) {
            int b = b0 + wb * 32 + mt * 16 + rr * 8 + lrow;
            #pragma unroll
            for (int nt = 0; nt < 2; nt++) {
                int jj = wj * 16 + nt * 8 + 2 * tg;
                size_t off = (size_t)b * NH + j0 + jj;
                float2 xv = *(const float2*)&x[off];
                float2 hv = *(const float2*)&h[off];
                float2 cv = *(const float2*)&c[off];
                float xa[2] = {xv.x, xv.y};
                float ha[2] = {hv.x, hv.y};
                float ca[2] = {cv.x, cv.y};
                float hn[2], cn[2];
                #pragma unroll
                for (int e = 0; e < 2; e++) {
                    int jc = jj + e;
                    int dr = rr * 2 + e;
                    int eb = ((mt * 2 + nt) * 2) * 4 + dr;
                    float gi = spill[eb * 256 + tid];
                    float gf = spill[(eb + 4) * 256 + tid];
                    float go = acc1[mt][nt][0][dr];
                    float gn = acc1[mt][nt][1][dr];
                    float base = epi[768 + jc] * xa[e] + epi[832 + jc] * ha[e];
                    float v0 = gi - xa[e] * epi[jc]       - ha[e] * epi[256 + jc] + epi[512 + jc] + base;
                    float v1 = gf - xa[e] * epi[64 + jc]  - ha[e] * epi[320 + jc] + epi[576 + jc] + base;
                    float v2 = go - xa[e] * epi[128 + jc] - ha[e] * epi[384 + jc] + epi[640 + jc] + base;
                    float v3 = gn - xa[e] * epi[192 + jc] - ha[e] * epi[448 + jc] + epi[704 + jc] + base;
                    float ig = sigm_f(v0);
                    float fg = sigm_f(v1);
                    float og = sigm_f(v2);
                    float ng = tanh_f(v3);
                    float cnx = fg * ca[e] + ig * ng;
                    cn[e] = cnx;
                    hn[e] = og * tanh_f(cnx);
                }
                *(float2*)&out[off] = make_float2(hn[0], hn[1]);
                *(float2*)&out[(size_t)NB * NH + off] = make_float2(cn[0], cn[1]);
            }
        }
    }
}

// ============================================================================
extern "C" void kernel_launch(void* const* d_in, const int* in_sizes, int n_in,
                              void* d_out, int out_size) {
    const float* x     = (const float*)d_in[0];
    const float* h     = (const float*)d_in[1];
    const float* c     = (const float*)d_in[2];
    const float* dia_x = (const float*)d_in[3];
    const float* dia_h = (const float*)d_in[4];
    const float* Ux    = (const float*)d_in[5];
    const float* Vx    = (const float*)d_in[6];
    const float* Uh0   = (const float*)d_in[7];
    const float* Vh0   = (const float*)d_in[8];
    const float* Uh1   = (const float*)d_in[9];
    const float* Vh1   = (const float*)d_in[10];
    const float* bx    = (const float*)d_in[11];
    const float* bh    = (const float*)d_in[12];
    float* out = (float*)d_out;

    cudaFuncSetAttribute(stage1_mma,
                         cudaFuncAttributeMaxDynamicSharedMemorySize, S1_DSMEM);
    cudaFuncSetAttribute(stage2_mma,
                         cudaFuncAttributeMaxDynamicSharedMemorySize, S2_DSMEM);

    pack_u_kernel<<<96, 256>>>(Ux, Uh0, Uh1);
    stage1_mma<<<dim3(64, 6), 256, S1_DSMEM>>>(x, h, Vx, Vh0, Vh1, Ux, Uh0,
                                               bx, bh);
    stage2_mma<<<dim3(16, 128), 256, S2_DSMEM>>>(x, h, c, dia_x, dia_h, out);
}

// round 14
// speedup vs baseline: 3.6834x; 1.2599x over previous
#include <cuda_runtime.h>
#include <cuda_fp16.h>
#include <cstdint>

// ============================================================================
// myVMLSTMCell fused low-rank LSTM — R14: fp16-split 2-pass (R13 + A-fill fix:
// all 256 threads fill the A chunk; the tid<128 guard left tiles 2,3 garbage).
// ============================================================================

typedef unsigned long long ull;

#define NB 8192
#define NH 1024

__device__ uint32_t g_Af[512*20*32*4];   // A frags fp16 (single)
__device__ uint32_t g_Wh[4*128*6*32*4];  // stage2 B frags fp16 hi
__device__ uint32_t g_Wl[4*128*6*32*4];  // stage2 B frags fp16 lo
__device__ uint32_t g_Uhi[24576*4];      // stage1 B frags fp16 hi
__device__ uint32_t g_Ulo[24576*4];
__device__ float g_cx[4*NH];
__device__ float g_ch[4*NH];
__device__ float g_cb[4*NH];

// ---- helpers ---------------------------------------------------------------
__device__ __forceinline__ float sigm_f(float v) {
    return __fdividef(1.f, 1.f + __expf(-v));
}
__device__ __forceinline__ float tanh_f(float v) {
    return 1.f - __fdividef(2.f, 1.f + __expf(2.f * v));
}
__device__ __forceinline__ void packsplit(float f0, float f1,
                                          uint32_t& hi, uint32_t& lo) {
    __half h0 = __float2half_rn(f0);
    __half h1 = __float2half_rn(f1);
    __half l0 = __float2half_rn(f0 - __half2float(h0));
    __half l1 = __float2half_rn(f1 - __half2float(h1));
    hi = (uint32_t)__half_as_ushort(h0) | ((uint32_t)__half_as_ushort(h1) << 16);
    lo = (uint32_t)__half_as_ushort(l0) | ((uint32_t)__half_as_ushort(l1) << 16);
}
__device__ __forceinline__ uint32_t packh2(float f0, float f1) {
    __half h0 = __float2half_rn(f0);
    __half h1 = __float2half_rn(f1);
    return (uint32_t)__half_as_ushort(h0) |
           ((uint32_t)__half_as_ushort(h1) << 16);
}
__device__ __forceinline__ uint32_t s2u(const void* p) {
    return (uint32_t)__cvta_generic_to_shared(p);
}
__device__ __forceinline__ void cp16(uint32_t dst, const void* src) {
    asm volatile("cp.async.cg.shared.global [%0], [%1], 16;\n"
                 :: "r"(dst), "l"(src));
}
__device__ __forceinline__ void cp_commit() {
    asm volatile("cp.async.commit_group;\n");
}
__device__ __forceinline__ void cp_wait0() {
    asm volatile("cp.async.wait_group 0;\n");
}
__device__ __forceinline__ void cp_wait1() {
    asm volatile("cp.async.wait_group 1;\n");
}
__device__ __forceinline__ void lds128(uint32_t* r, uint32_t a) {
    asm volatile("ld.shared.v4.b32 {%0,%1,%2,%3}, [%4];"
                 : "=r"(r[0]), "=r"(r[1]), "=r"(r[2]), "=r"(r[3]) : "r"(a));
}
__device__ __forceinline__ void sts32(uint32_t a, uint32_t v) {
    asm volatile("st.shared.b32 [%0], %1;" :: "r"(a), "r"(v));
}
__device__ __forceinline__ void mma_f16(float* d, const uint32_t* a,
                                        const uint32_t* b) {
    asm volatile(
        "mma.sync.aligned.m16n8k16.row.col.f32.f16.f16.f32 "
        "{%0,%1,%2,%3}, {%4,%5,%6,%7}, {%8,%9}, {%0,%1,%2,%3};\n"
        : "+f"(d[0]), "+f"(d[1]), "+f"(d[2]), "+f"(d[3])
        : "r"(a[0]), "r"(a[1]), "r"(a[2]), "r"(a[3]), "r"(b[0]), "r"(b[1]));
}

// ============================================================================
// pack_u: stage1 B frags fp16 hi/lo. 96 blocks x 256.
// ============================================================================
__global__ void pack_u_kernel(const float* __restrict__ Ux,
                              const float* __restrict__ Uh0,
                              const float* __restrict__ Uh1) {
    int idx = blockIdx.x * 256 + threadIdx.x;
    if (idx >= 24576) return;
    const float* src;
    int lane, tg, n, cc;
    if (idx < 8192) {
        int n8 = idx >> 10; cc = (idx >> 5) & 31; lane = idx & 31;
        n = n8 * 8 + (lane >> 2);
        src = Ux;
    } else {
        int rem = idx - 8192;
        int e = rem >> 12;
        int n8 = (rem >> 9) & 7; cc = (rem >> 5) & 15; lane = rem & 31;
        n = n8 * 8 + (lane >> 2);
        src = ((e & 1) ? Uh1 : Uh0) + (e >> 1) * 512 * 64;
    }
    tg = lane & 3;
    uint32_t hi[4], lo[4];
    #pragma unroll
    for (int t = 0; t < 4; t++) {
        int kp = cc * 16 + tg + t * 4;
        packsplit(src[(size_t)(2 * kp) * 64 + n],
                  src[(size_t)(2 * kp + 1) * 64 + n], hi[t], lo[t]);
    }
    *(uint4*)&g_Uhi[(size_t)idx * 4] = make_uint4(hi[0], hi[1], hi[2], hi[3]);
    *(uint4*)&g_Ulo[(size_t)idx * 4] = make_uint4(lo[0], lo[1], lo[2], lo[3]);
}

// ============================================================================
// stage1_mma: grid (64, 6).
//   y<5 : GEMM 128b x 64n, fp16 2-pass, conflict-free frag smem
//   y==5: pack_w (fp16 split) + coef (warp-per-entry reduce)
//   buf (16384B): A[0,8K) W_hi[8K,12K) W_lo[12K,16K)
// ============================================================================
#define S1_DSMEM (2*16384 + 16384)

__global__ __launch_bounds__(256, 2)
void stage1_mma(const float* __restrict__ x, const float* __restrict__ h,
                const float* __restrict__ Vx, const float* __restrict__ Vh0,
                const float* __restrict__ Vh1, const float* __restrict__ Ux,
                const float* __restrict__ Uh0, const float* __restrict__ bx,
                const float* __restrict__ bh) {
    extern __shared__ char dsm[];
    uint32_t smu = s2u(dsm);

    int tid = threadIdx.x;
    int lane = tid & 31, wid = tid >> 5;
    int tg = lane & 3, lrow = lane >> 2;

    if (blockIdx.y == 5) {
        // ================== pack_w + coef ==================
        float (*V)[64] = (float(*)[64])dsm;   // 192x64 = 48KB
        int blk = blockIdx.x;
        int jblk = blk & 15, kap = blk >> 4;
        int g = kap >> 1;
        int mh0 = (((kap ^ 1) & 1) << 10) + jblk * 64;

        #pragma unroll
        for (int i = 0; i < 4; i++) {
            int idx = tid + i * 256;
            int jl = idx >> 4, kq = idx & 15;
            float4 v = *(const float4*)
                &Vx[((size_t)(kap * NH + jblk * 64 + jl)) * 64 + kq * 4];
            V[kq * 4 + 0][jl] = v.x;
            V[kq * 4 + 1][jl] = v.y;
            V[kq * 4 + 2][jl] = v.z;
            V[kq * 4 + 3][jl] = v.w;
        }
        #pragma unroll
        for (int i = 0; i < 8; i++) {
            int idx = tid + i * 256;
            int kkr = idx >> 4, jq = idx & 15;
            const float* src = (kkr < 64)
                ? &Vh0[(size_t)g * 131072 + kkr * 2048 + mh0]
                : &Vh1[(size_t)g * 131072 + (kkr - 64) * 2048 + mh0];
            *(float4*)&V[64 + kkr][jq * 4] = *(const float4*)&src[jq * 4];
        }
        __syncthreads();
        #pragma unroll
        for (int i = 0; i < 6; i++) {
            int idx = tid + i * 256;
            int n8l = idx / 192, rem = idx % 192;
            int cc = rem >> 5, ln = rem & 31;
            int jl = n8l * 8 + (ln >> 2), tgw = ln & 3;
            uint32_t hi[4], lo[4];
            #pragma unroll
            for (int t = 0; t < 4; t++) {
                int kk = 2 * (cc * 16 + tgw + t * 4);
                packsplit(V[kk][jl], V[kk + 1][jl], hi[t], lo[t]);
            }
            size_t fo = (((size_t)kap * 128 + jblk * 8 + n8l) * 6 + cc) * 32 + ln;
            *(uint4*)&g_Wh[fo * 4] = make_uint4(hi[0], hi[1], hi[2], hi[3]);
            *(uint4*)&g_Wl[fo * 4] = make_uint4(lo[0], lo[1], lo[2], lo[3]);
        }
        // ---- coef: 64 entries per block, warp-per-entry ----
        int base = blk * 64;
        #pragma unroll 1
        for (int t8 = 0; t8 < 8; t8++) {
            int idx = base + wid * 8 + t8;
            int j = idx & 1023;
            int kapc = idx >> 10;
            int gc = kapc >> 1;
            int mh = (((kapc ^ 1) & 1) << 10) + j;
            float sx = 0.f, sh = 0.f;
            #pragma unroll
            for (int rr = 0; rr < 2; rr++) {
                int r = lane + rr * 32;
                sx += Ux[j * 64 + r] * Vx[(size_t)(kapc * NH + j) * 64 + r];
                sh += Uh0[j * 64 + r]
                    * Vh0[(size_t)gc * 131072 + (size_t)r * 2048 + mh];
            }
            #pragma unroll
            for (int o = 16; o; o >>= 1) {
                sx += __shfl_xor_sync(0xFFFFFFFFu, sx, o);
                sh += __shfl_xor_sync(0xFFFFFFFFu, sh, o);
            }
            if (lane == 0) {
                g_cx[idx] = sx;
                g_ch[idx] = sh;
                g_cb[idx] = bx[(kapc << 10) + j] + bh[((kapc ^ 1) << 10) + j];
            }
        }
        return;
    }

    // ================== GEMM path ==================
    int laneT = tg * 8 + lrow;
    int wb = wid >> 1, wj = wid & 1;
    int b0 = blockIdx.x * 128;
    int cb = blockIdx.y;

    const float* Ap;
    int NC, NCC, ufrag, aoff, outoff;
    if (cb == 0) {
        Ap = x; NC = 32; NCC = 32; ufrag = 0; aoff = 0; outoff = 0;
    } else {
        int e = cb - 1;
        int g = e >> 1, i = e & 1;
        Ap = h; NC = 16; NCC = 16;
        ufrag = 8192 + e * 4096;
        aoff = ((g + i) & 1) * 512;
        outoff = 64 + g * 128 + i * 64;
    }

    float4 pf[4];
    int arow = tid >> 1, acg = tid & 1;

    #define S1_LDG(cc) do {                                                   \
        const float* src = &Ap[(size_t)(b0 + arow) * NH + aoff +              \
                               (cc) * 32 + acg * 16];                         \
        pf[0] = *(const float4*)(src);                                        \
        pf[1] = *(const float4*)(src + 4);                                    \
        pf[2] = *(const float4*)(src + 8);                                    \
        pf[3] = *(const float4*)(src + 12);                                   \
    } while (0)

    #define S1_STS(buf) do {                                                  \
        uint32_t bufb = smu + (buf) * 16384;                                  \
        const float* pff = (const float*)pf;                                  \
        uint32_t tb = bufb + (uint32_t)(((arow >> 4) * 2 + acg) * 512);       \
        uint32_t rb = (arow >> 3) & 1;                                        \
        _Pragma("unroll")                                                     \
        for (int q = 0; q < 8; q++) {                                         \
            uint32_t hv = packh2(pff[2 * q], pff[2 * q + 1]);                 \
            uint32_t ltp = (uint32_t)((q & 3) * 8 + (arow & 7));              \
            uint32_t sl  = (uint32_t)(((q >> 2) << 1) + rb);                  \
            uint32_t slp = (sl + 2 * (uint32_t)acg) & 3;                      \
            sts32(tb + ltp * 16 + slp * 4, hv);                               \
        }                                                                     \
    } while (0)

    #define S1_CPW(cc, buf) do {                                              \
        int n8 = tid >> 5, ln = tid & 31;                                     \
        uint32_t dst = smu + (buf) * 16384 + 8192 + (n8 * 32 + ln) * 16;      \
        size_t fo = (size_t)(ufrag + (n8 * NCC + (cc)) * 32 + ln) * 4;        \
        cp16(dst, &g_Uhi[fo]);                                                \
        cp16(dst + 4096, &g_Ulo[fo]);                                         \
        cp_commit();                                                          \
    } while (0)

    #define S1_COMPUTE(buf) do {                                              \
        uint32_t bufb = smu + (buf) * 16384;                                  \
        uint32_t bhf[4][4], blf[4][4];                                        \
        _Pragma("unroll")                                                     \
        for (int nt = 0; nt < 4; nt++) {                                      \
            uint32_t ba = bufb + 8192 + (((wj * 4 + nt) * 32) + lane) * 16;   \
            lds128(bhf[nt], ba);                                              \
            lds128(blf[nt], ba + 4096);                                       \
        }                                                                     \
        _Pragma("unroll")                                                     \
        for (int s = 0; s < 2; s++) {                                         \
            uint32_t af[2][4];                                                \
            _Pragma("unroll")                                                 \
            for (int mt = 0; mt < 2; mt++) {                                  \
                uint32_t rh[4];                                               \
                uint32_t aa = bufb +                                          \
                    ((((wb * 2 + mt) * 2 + s) * 32) + laneT) * 16;            \
                lds128(rh, aa);                                               \
                _Pragma("unroll")                                             \
                for (int i = 0; i < 4; i++)                                   \
                    af[mt][i] = rh[(i + 2 * s) & 3];                          \
            }                                                                 \
            _Pragma("unroll")                                                 \
            for (int nt = 0; nt < 4; nt++) {                                  \
                uint32_t b2h[2] = {bhf[nt][s * 2], bhf[nt][s * 2 + 1]};       \
                uint32_t b2l[2] = {blf[nt][s * 2], blf[nt][s * 2 + 1]};       \
                _Pragma("unroll")                                             \
                for (int mt = 0; mt < 2; mt++) {                              \
                    mma_f16(acc[mt][nt], af[mt], b2h);                        \
                    mma_f16(acc[mt][nt], af[mt], b2l);                        \
                }                                                             \
            }                                                                 \
        }                                                                     \
    } while (0)

    float acc[2][4][4];
    #pragma unroll
    for (int a1 = 0; a1 < 2; a1++)
        #pragma unroll
        for (int a2 = 0; a2 < 4; a2++)
            #pragma unroll
            for (int a3 = 0; a3 < 4; a3++) acc[a1][a2][a3] = 0.f;

    S1_LDG(0);
    S1_CPW(0, 0);
    S1_STS(0);
    cp_wait0();
    __syncthreads();

    for (int cc = 0; cc < NC; cc++) {
        int buf = cc & 1;
        if (cc < NC - 1) {
            S1_CPW(cc + 1, buf ^ 1);
            S1_LDG(cc + 1);
        }
        S1_COMPUTE(buf);
        if (cc < NC - 1) {
            S1_STS(buf ^ 1);
            cp_wait0();
        }
        __syncthreads();
    }

    // epilogue: C-frags -> g_Af (fp16 single), 1 STG.128 per (mt,ntp)
    #pragma unroll
    for (int mt = 0; mt < 2; mt++) {
        int b16g = (b0 + wb * 32 + mt * 16) >> 4;
        #pragma unroll
        for (int ntp = 0; ntp < 2; ntp++) {
            int k16g = (outoff >> 4) + wj * 2 + ntp;
            uint4 v;
            v.x = packh2(acc[mt][2 * ntp][0],     acc[mt][2 * ntp][1]);
            v.y = packh2(acc[mt][2 * ntp][2],     acc[mt][2 * ntp][3]);
            v.z = packh2(acc[mt][2 * ntp + 1][0], acc[mt][2 * ntp + 1][1]);
            v.w = packh2(acc[mt][2 * ntp + 1][2], acc[mt][2 * ntp + 1][3]);
            size_t fo = ((size_t)b16g * 20 + k16g) * 32 + lane;
            *(uint4*)&g_Af[fo * 4] = v;
        }
    }
}

// ============================================================================
// stage2_mma: fp16 2-pass, 3-stage cp.async pipeline, fused LSTM epilogue.
//   buf (20480B): A[0,4K) W_hi[4K,12K) W_lo[12K,20K)
//   A fill: ALL 256 threads (4 b16 x 2 k16 x 32 lanes = 256 frags).
// ============================================================================
#define S2_DSMEM (3*20480 + 32768)

__global__ __launch_bounds__(256, 2)
void stage2_mma(const float* __restrict__ x, const float* __restrict__ h,
                const float* __restrict__ c, const float* __restrict__ dia_x,
                const float* __restrict__ dia_h, float* __restrict__ out) {
    extern __shared__ char dsm[];
    __shared__ float epi[896];
    uint32_t smu = s2u(dsm);
    float* spill = (float*)(dsm + 3 * 20480);

    int tid = threadIdx.x;
    int lane = tid & 31, wid = tid >> 5;
    int tg = lane & 3, lrow = lane >> 2;
    int wb = wid >> 2, wj = wid & 3;
    int j0 = blockIdx.x * 64;
    int b0 = blockIdx.y * 64;
    int b16base = b0 >> 4;
    int n8base = j0 >> 3;

    for (int i = tid; i < 896; i += 256) {
        float v;
        if (i < 256)       v = g_cx[(i >> 6) * 1024 + j0 + (i & 63)];
        else if (i < 512)  { int q = i - 256; v = g_ch[(q >> 6) * 1024 + j0 + (q & 63)]; }
        else if (i < 768)  { int q = i - 512; v = g_cb[(q >> 6) * 1024 + j0 + (q & 63)]; }
        else if (i < 832)  v = dia_x[j0 + i - 768];
        else               v = dia_h[j0 + i - 832];
        epi[i] = v;
    }

    #define FILL(buf, p, cc) do {                                             \
        uint32_t bufb = smu + (buf) * 20480;                                  \
        int k16base = ((cc) < 2) ? (cc) * 2 : (p) * 8 + (cc) * 2;             \
        {                                                                     \
            int b16l = tid >> 6, k16l = (tid >> 5) & 1, ln = tid & 31;        \
            size_t fo = (size_t)(((b16base + b16l) * 20 + k16base + k16l)     \
                                 * 32 + ln) * 4;                              \
            uint32_t dst = bufb + ((b16l * 2 + k16l) * 32 + ln) * 16;         \
            cp16(dst, &g_Af[fo]);                                             \
        }                                                                     \
        _Pragma("unroll")                                                     \
        for (int i2 = 0; i2 < 2; i2++) {                                      \
            int idx = tid + i2 * 256;                                         \
            int gl = idx >> 8, n8 = (idx >> 5) & 7, ln = idx & 31;            \
            size_t fo = (size_t)((((2 * (p) + gl) * 128 + n8base + n8) * 6    \
                                  + (cc)) * 32 + ln) * 4;                     \
            uint32_t dst = bufb + 4096 + ((gl * 8 + n8) * 32 + ln) * 16;      \
            cp16(dst, &g_Wh[fo]);                                             \
            cp16(dst + 8192, &g_Wl[fo]);                                      \
        }                                                                     \
        cp_commit();                                                          \
    } while (0)

    #define COMPUTE(ACC, buf) do {                                            \
        uint32_t bufb = smu + (buf) * 20480;                                  \
        uint32_t bhf[2][2][4], blf[2][2][4];                                  \
        _Pragma("unroll")                                                     \
        for (int gl = 0; gl < 2; gl++)                                        \
            _Pragma("unroll")                                                 \
            for (int nt = 0; nt < 2; nt++) {                                  \
                uint32_t ba = bufb + 4096 +                                   \
                    ((gl * 8 + wj * 2 + nt) * 32 + lane) * 16;                \
                lds128(bhf[gl][nt], ba);                                      \
                lds128(blf[gl][nt], ba + 8192);                               \
            }                                                                 \
        _Pragma("unroll")                                                     \
        for (int s = 0; s < 2; s++) {                                         \
            uint32_t af[2][4];                                                \
            _Pragma("unroll")                                                 \
            for (int mt = 0; mt < 2; mt++) {                                  \
                uint32_t aa = bufb +                                          \
                    (((wb * 2 + mt) * 2 + s) * 32 + lane) * 16;               \
                lds128(af[mt], aa);                                           \
            }                                                                 \
            _Pragma("unroll")                                                 \
            for (int gl = 0; gl < 2; gl++)                                    \
                _Pragma("unroll")                                             \
                for (int nt = 0; nt < 2; nt++) {                              \
                    uint32_t b2h[2] = {bhf[gl][nt][s * 2], bhf[gl][nt][s * 2 + 1]}; \
                    uint32_t b2l[2] = {blf[gl][nt][s * 2], blf[gl][nt][s * 2 + 1]}; \
                    _Pragma("unroll")                                         \
                    for (int mt = 0; mt < 2; mt++) {                          \
                        mma_f16(ACC[mt][nt][gl], af[mt], b2h);                \
                        mma_f16(ACC[mt][nt][gl], af[mt], b2l);                \
                    }                                                         \
                }                                                             \
        }                                                                     \
    } while (0)

    FILL(0, 0, 0);
    FILL(1, 0, 1);

    // ---------------- phase 0 (gates i,f) ----------------
    {
        float acc0[2][2][2][4];
        #pragma unroll
        for (int a1 = 0; a1 < 2; a1++)
            #pragma unroll
            for (int a2 = 0; a2 < 2; a2++)
                #pragma unroll
                for (int a3 = 0; a3 < 2; a3++)
                    #pragma unroll
                    for (int a4 = 0; a4 < 4; a4++) acc0[a1][a2][a3][a4] = 0.f;

        for (int ci = 0; ci < 6; ci++) {
            cp_wait1();
            __syncthreads();
            int nc = ci + 2;
            FILL(nc % 3, nc / 6, nc % 6);
            COMPUTE(acc0, ci % 3);
        }
        #pragma unroll
        for (int mt = 0; mt < 2; mt++)
            #pragma unroll
            for (int nt = 0; nt < 2; nt++)
                #pragma unroll
                for (int gl = 0; gl < 2; gl++)
                    #pragma unroll
                    for (int dr = 0; dr < 4; dr++) {
                        int e = ((mt * 2 + nt) * 2 + gl) * 4 + dr;
                        spill[e * 256 + tid] = acc0[mt][nt][gl][dr];
                    }
    }

    // ---------------- phase 1 (gates o,n) ----------------
    float acc1[2][2][2][4];
    #pragma unroll
    for (int a1 = 0; a1 < 2; a1++)
        #pragma unroll
        for (int a2 = 0; a2 < 2; a2++)
            #pragma unroll
            for (int a3 = 0; a3 < 2; a3++)
                #pragma unroll
                for (int a4 = 0; a4 < 4; a4++) acc1[a1][a2][a3][a4] = 0.f;

    for (int ci = 6; ci < 12; ci++) {
        if (ci < 11) cp_wait1(); else cp_wait0();
        __syncthreads();
        int nc = ci + 2;
        if (nc < 12) FILL(nc % 3, 1, nc % 6);
        COMPUTE(acc1, ci % 3);
    }

    // ---- fused LSTM epilogue ------------------------------------------------
    #pragma unroll
    for (int mt = 0; mt < 2; mt++) {
        #pragma unroll
        for (int rr = 0; rr < 2; rr++) {
            int b = b0 + wb * 32 + mt * 16 + rr * 8 + lrow;
            #pragma unroll
            for (int nt = 0; nt < 2; nt++) {
                int jj = wj * 16 + nt * 8 + 2 * tg;
                size_t off = (size_t)b * NH + j0 + jj;
                float2 xv = *(const float2*)&x[off];
                float2 hv = *(const float2*)&h[off];
                float2 cv = *(const float2*)&c[off];
                float xa[2] = {xv.x, xv.y};
                float ha[2] = {hv.x, hv.y};
                float ca[2] = {cv.x, cv.y};
                float hn[2], cn[2];
                #pragma unroll
                for (int e = 0; e < 2; e++) {
                    int jc = jj + e;
                    int dr = rr * 2 + e;
                    int eb = ((mt * 2 + nt) * 2) * 4 + dr;
                    float gi = spill[eb * 256 + tid];
                    float gf = spill[(eb + 4) * 256 + tid];
                    float go = acc1[mt][nt][0][dr];
                    float gn = acc1[mt][nt][1][dr];
                    float base = epi[768 + jc] * xa[e] + epi[832 + jc] * ha[e];
                    float v0 = gi - xa[e] * epi[jc]       - ha[e] * epi[256 + jc] + epi[512 + jc] + base;
                    float v1 = gf - xa[e] * epi[64 + jc]  - ha[e] * epi[320 + jc] + epi[576 + jc] + base;
                    float v2 = go - xa[e] * epi[128 + jc] - ha[e] * epi[384 + jc] + epi[640 + jc] + base;
                    float v3 = gn - xa[e] * epi[192 + jc] - ha[e] * epi[448 + jc] + epi[704 + jc] + base;
                    float ig = sigm_f(v0);
                    float fg = sigm_f(v1);
                    float og = sigm_f(v2);
                    float ng = tanh_f(v3);
                    float cnx = fg * ca[e] + ig * ng;
                    cn[e] = cnx;
                    hn[e] = og * tanh_f(cnx);
                }
                *(float2*)&out[off] = make_float2(hn[0], hn[1]);
                *(float2*)&out[(size_t)NB * NH + off] = make_float2(cn[0], cn[1]);
            }
        }
    }
}

// ============================================================================
extern "C" void kernel_launch(void* const* d_in, const int* in_sizes, int n_in,
                              void* d_out, int out_size) {
    const float* x     = (const float*)d_in[0];
    const float* h     = (const float*)d_in[1];
    const float* c     = (const float*)d_in[2];
    const float* dia_x = (const float*)d_in[3];
    const float* dia_h = (const float*)d_in[4];
    const float* Ux    = (const float*)d_in[5];
    const float* Vx    = (const float*)d_in[6];
    const float* Uh0   = (const float*)d_in[7];
    const float* Vh0   = (const float*)d_in[8];
    const float* Uh1   = (const float*)d_in[9];
    const float* Vh1   = (const float*)d_in[10];
    const float* bx    = (const float*)d_in[11];
    const float* bh    = (const float*)d_in[12];
    float* out = (float*)d_out;

    cudaFuncSetAttribute(stage1_mma,
                         cudaFuncAttributeMaxDynamicSharedMemorySize, S1_DSMEM);
    cudaFuncSetAttribute(stage2_mma,
                         cudaFuncAttributeMaxDynamicSharedMemorySize, S2_DSMEM);

    pack_u_kernel<<<96, 256>>>(Ux, Uh0, Uh1);
    stage1_mma<<<dim3(64, 6), 256, S1_DSMEM>>>(x, h, Vx, Vh0, Vh1, Ux, Uh0,
                                               bx, bh);
    stage2_mma<<<dim3(16, 128), 256, S2_DSMEM>>>(x, h, c, dia_x, dia_h, out);
}